// round 1
// baseline (speedup 1.0000x reference)
#include <cuda_runtime.h>
#include <math.h>
#include <float.h>

#define NN 4096
#define DD 2048
#define HH 256
#define HEADS 4

// ---------------- static device scratch (no cudaMalloc allowed) ----------------
__device__ float g_Q[NN * HH];
__device__ float g_K[NN * HH];
__device__ float g_qn[NN];
__device__ float g_kn[NN];
__device__ float g_md[NN];    // md + 1e-10
__device__ float g_kth[NN];   // 30th-largest affinity value
__device__ float g_A[(size_t)NN * NN];   // gram -> aff
__device__ float g_P[(size_t)NN * NN];   // A + A^T -> softmax rows (P)
__device__ float g_P2[(size_t)NN * NN];  // P @ P
__device__ float g_Y[NN * DD];
__device__ float g_Y2[NN * DD];

// ---------------- zero output ----------------
__global__ void zero_kernel(float* out, int n) {
    int i = blockIdx.x * blockDim.x + threadIdx.x;
    if (i < n) out[i] = 0.0f;
}

// ---------------- GEMM NN: C[M,N] = alpha * A[M,K] @ B[K,N] + beta*C ----------------
__global__ __launch_bounds__(256) void gemm_nn_kernel(
    const float* __restrict__ A, const float* __restrict__ B, float* __restrict__ C,
    int M, int N, int K, float alpha, float beta)
{
    __shared__ __align__(16) float As[8][128];
    __shared__ __align__(16) float Bs[8][128];
    const int tid = threadIdx.x;
    const int tx = tid & 15;
    const int ty = tid >> 4;
    const int m0 = blockIdx.y * 128;
    const int n0 = blockIdx.x * 128;
    const int arow = tid >> 1;
    const int acol = (tid & 1) << 2;
    const int brow = tid >> 5;
    const int bcol = (tid & 31) << 2;
    const float* Ap = A + (size_t)(m0 + arow) * K + acol;
    const float* Bp = B + (size_t)brow * N + n0 + bcol;

    float acc[8][8];
    #pragma unroll
    for (int i = 0; i < 8; i++)
        #pragma unroll
        for (int j = 0; j < 8; j++) acc[i][j] = 0.0f;

    for (int k0 = 0; k0 < K; k0 += 8) {
        float4 av = *(const float4*)(Ap + k0);
        As[acol + 0][arow] = av.x;
        As[acol + 1][arow] = av.y;
        As[acol + 2][arow] = av.z;
        As[acol + 3][arow] = av.w;
        *(float4*)&Bs[brow][bcol] = *(const float4*)(Bp + (size_t)k0 * N);
        __syncthreads();
        #pragma unroll
        for (int kk = 0; kk < 8; kk++) {
            float a[8], b[8];
            *(float4*)&a[0] = *(const float4*)&As[kk][ty << 3];
            *(float4*)&a[4] = *(const float4*)&As[kk][(ty << 3) + 4];
            *(float4*)&b[0] = *(const float4*)&Bs[kk][tx << 3];
            *(float4*)&b[4] = *(const float4*)&Bs[kk][(tx << 3) + 4];
            #pragma unroll
            for (int i = 0; i < 8; i++)
                #pragma unroll
                for (int j = 0; j < 8; j++)
                    acc[i][j] = fmaf(a[i], b[j], acc[i][j]);
        }
        __syncthreads();
    }
    #pragma unroll
    for (int i = 0; i < 8; i++) {
        float* Cp = C + (size_t)(m0 + (ty << 3) + i) * N + n0 + (tx << 3);
        #pragma unroll
        for (int j = 0; j < 8; j++) {
            float v = alpha * acc[i][j];
            if (beta != 0.0f) v = fmaf(beta, Cp[j], v);
            Cp[j] = v;
        }
    }
}

// ---------------- GEMM NT: C[M,N] = A[M,K] @ B[N,K]^T (+ bias[n]) ----------------
__global__ __launch_bounds__(256) void gemm_nt_kernel(
    const float* __restrict__ A, const float* __restrict__ B, float* __restrict__ C,
    int M, int N, int K, const float* __restrict__ bias)
{
    __shared__ __align__(16) float As[8][128];
    __shared__ __align__(16) float Bs[8][128];
    const int tid = threadIdx.x;
    const int tx = tid & 15;
    const int ty = tid >> 4;
    const int m0 = blockIdx.y * 128;
    const int n0 = blockIdx.x * 128;
    const int arow = tid >> 1;
    const int acol = (tid & 1) << 2;
    const float* Ap = A + (size_t)(m0 + arow) * K + acol;
    const float* Bp = B + (size_t)(n0 + arow) * K + acol;

    float acc[8][8];
    #pragma unroll
    for (int i = 0; i < 8; i++)
        #pragma unroll
        for (int j = 0; j < 8; j++) acc[i][j] = 0.0f;

    for (int k0 = 0; k0 < K; k0 += 8) {
        float4 av = *(const float4*)(Ap + k0);
        As[acol + 0][arow] = av.x;
        As[acol + 1][arow] = av.y;
        As[acol + 2][arow] = av.z;
        As[acol + 3][arow] = av.w;
        float4 bv = *(const float4*)(Bp + k0);
        Bs[acol + 0][arow] = bv.x;
        Bs[acol + 1][arow] = bv.y;
        Bs[acol + 2][arow] = bv.z;
        Bs[acol + 3][arow] = bv.w;
        __syncthreads();
        #pragma unroll
        for (int kk = 0; kk < 8; kk++) {
            float a[8], b[8];
            *(float4*)&a[0] = *(const float4*)&As[kk][ty << 3];
            *(float4*)&a[4] = *(const float4*)&As[kk][(ty << 3) + 4];
            *(float4*)&b[0] = *(const float4*)&Bs[kk][tx << 3];
            *(float4*)&b[4] = *(const float4*)&Bs[kk][(tx << 3) + 4];
            #pragma unroll
            for (int i = 0; i < 8; i++)
                #pragma unroll
                for (int j = 0; j < 8; j++)
                    acc[i][j] = fmaf(a[i], b[j], acc[i][j]);
        }
        __syncthreads();
    }
    #pragma unroll
    for (int i = 0; i < 8; i++) {
        float* Cp = C + (size_t)(m0 + (ty << 3) + i) * N + n0 + (tx << 3);
        #pragma unroll
        for (int j = 0; j < 8; j++) {
            float v = acc[i][j];
            if (bias) v += bias[n0 + (tx << 3) + j];
            Cp[j] = v;
        }
    }
}

// ---------------- row squared norms of Q and K ----------------
__global__ void rownorm_kernel(const float* __restrict__ Q, const float* __restrict__ K,
                               float* __restrict__ qn, float* __restrict__ kn)
{
    int i = blockIdx.x;
    int tid = threadIdx.x;  // 256 = HH
    __shared__ float sq[256];
    __shared__ float sk[256];
    float q = Q[(size_t)i * HH + tid];
    float k = K[(size_t)i * HH + tid];
    sq[tid] = q * q;
    sk[tid] = k * k;
    __syncthreads();
    for (int s = 128; s > 0; s >>= 1) {
        if (tid < s) { sq[tid] += sq[tid + s]; sk[tid] += sk[tid + s]; }
        __syncthreads();
    }
    if (tid == 0) { qn[i] = sq[0]; kn[i] = sk[0]; }
}

// ---------------- per-row selection: 30 smallest distances ----------------
// md = 11th smallest dist + 1e-10 ; kth = exp(-((30th smallest dist)/md)^2)
__global__ void select_kernel(const float* __restrict__ G,
                              const float* __restrict__ qn, const float* __restrict__ kn,
                              float* __restrict__ md_out, float* __restrict__ kth_out)
{
    int i = blockIdx.x;
    int tid = threadIdx.x;  // 256
    __shared__ float sd[NN];
    __shared__ float rmin[256];
    __shared__ int ridx[256];
    __shared__ float sel[30];
    float qni = qn[i];
    const float* Gi = G + (size_t)i * NN;
    for (int j = tid; j < NN; j += 256) {
        float sq = qni + kn[j] - 2.0f * Gi[j];
        sd[j] = sqrtf(fmaxf(sq, 0.0f) + 1e-10f);
    }
    __syncthreads();
    for (int it = 0; it < 30; it++) {
        float mv = FLT_MAX;
        int mi = -1;
        for (int j = tid; j < NN; j += 256) {
            float v = sd[j];
            if (v < mv) { mv = v; mi = j; }
        }
        rmin[tid] = mv;
        ridx[tid] = mi;
        __syncthreads();
        for (int s = 128; s > 0; s >>= 1) {
            if (tid < s) {
                float v2 = rmin[tid + s];
                if (v2 < rmin[tid] || (v2 == rmin[tid] && ridx[tid + s] < ridx[tid])) {
                    rmin[tid] = v2;
                    ridx[tid] = ridx[tid + s];
                }
            }
            __syncthreads();
        }
        if (tid == 0) {
            sel[it] = rmin[0];
            sd[ridx[0]] = FLT_MAX;
        }
        __syncthreads();
    }
    if (tid == 0) {
        float mdp = sel[10] + 1e-10f;
        float t = sel[29] / mdp;
        md_out[i] = mdp;
        kth_out[i] = expf(-(t * t));
    }
}

// ---------------- affinity + knn prune + diag=1, in place over gram ----------------
__global__ void aff_kernel(float* __restrict__ A,
                           const float* __restrict__ qn, const float* __restrict__ kn,
                           const float* __restrict__ mdp, const float* __restrict__ kth)
{
    size_t idx = (size_t)blockIdx.x * blockDim.x + threadIdx.x;
    if (idx >= (size_t)NN * NN) return;
    int i = (int)(idx >> 12);   // /4096
    int j = (int)(idx & 4095);
    float sq = qn[i] + kn[j] - 2.0f * A[idx];
    float d = sqrtf(fmaxf(sq, 0.0f) + 1e-10f);
    float dd = d / mdp[i];
    float a = expf(-(dd * dd));
    float r = (a >= kth[i]) ? a : 0.0f;
    if (j == i) r = 1.0f;
    A[idx] = r;
}

// ---------------- B = A + A^T ----------------
__global__ void transadd_kernel(const float* __restrict__ A, float* __restrict__ B)
{
    __shared__ float tile[32][33];
    int x0 = blockIdx.x * 32;
    int y0 = blockIdx.y * 32;
    int tx = threadIdx.x;   // 32
    int ty = threadIdx.y;   // 8
    for (int r = ty; r < 32; r += 8)
        tile[r][tx] = A[(size_t)(x0 + r) * NN + y0 + tx];
    __syncthreads();
    for (int r = ty; r < 32; r += 8) {
        size_t idx = (size_t)(y0 + r) * NN + x0 + tx;
        B[idx] = A[idx] + tile[tx][r];
    }
}

// ---------------- row softmax in place ----------------
__global__ void softmax_kernel(float* __restrict__ P)
{
    int i = blockIdx.x;
    int tid = threadIdx.x;  // 256
    __shared__ float s[NN];
    __shared__ float red[256];
    size_t base = (size_t)i * NN;
    float m = -FLT_MAX;
    for (int j = tid; j < NN; j += 256) {
        float v = P[base + j];
        s[j] = v;
        m = fmaxf(m, v);
    }
    red[tid] = m;
    __syncthreads();
    for (int st = 128; st > 0; st >>= 1) {
        if (tid < st) red[tid] = fmaxf(red[tid], red[tid + st]);
        __syncthreads();
    }
    m = red[0];
    __syncthreads();
    float sum = 0.0f;
    for (int j = tid; j < NN; j += 256) {
        float e = expf(s[j] - m);
        s[j] = e;
        sum += e;
    }
    red[tid] = sum;
    __syncthreads();
    for (int st = 128; st > 0; st >>= 1) {
        if (tid < st) red[tid] += red[tid + st];
        __syncthreads();
    }
    float inv = 1.0f / red[0];
    for (int j = tid; j < NN; j += 256)
        P[base + j] = s[j] * inv;
}

// ---------------- launch ----------------
extern "C" void kernel_launch(void* const* d_in, const int* in_sizes, int n_in,
                              void* d_out, int out_size)
{
    const float* X  = (const float*)d_in[0];
    const float* Wq = (const float*)d_in[1];
    const float* bq = (const float*)d_in[2];
    const float* Wk = (const float*)d_in[3];
    const float* bk = (const float*)d_in[4];
    float* out = (float*)d_out;

    float *Q, *K, *qn, *kn, *md, *kth, *A, *P, *P2, *Y, *Y2;
    cudaGetSymbolAddress((void**)&Q,  g_Q);
    cudaGetSymbolAddress((void**)&K,  g_K);
    cudaGetSymbolAddress((void**)&qn, g_qn);
    cudaGetSymbolAddress((void**)&kn, g_kn);
    cudaGetSymbolAddress((void**)&md, g_md);
    cudaGetSymbolAddress((void**)&kth, g_kth);
    cudaGetSymbolAddress((void**)&A,  g_A);
    cudaGetSymbolAddress((void**)&P,  g_P);
    cudaGetSymbolAddress((void**)&P2, g_P2);
    cudaGetSymbolAddress((void**)&Y,  g_Y);
    cudaGetSymbolAddress((void**)&Y2, g_Y2);

    zero_kernel<<<(NN * DD + 255) / 256, 256>>>(out, NN * DD);

    for (int h = 0; h < HEADS; h++) {
        const float* Wqh = Wq + (size_t)h * HH * DD;
        const float* Wkh = Wk + (size_t)h * HH * DD;
        const float* bqh = bq + (size_t)h * HH;
        const float* bkh = bk + (size_t)h * HH;

        // projections: Q = X @ Wq_h^T + bq_h, K likewise
        gemm_nt_kernel<<<dim3(HH / 128, NN / 128), 256>>>(X, Wqh, Q, NN, HH, DD, bqh);
        gemm_nt_kernel<<<dim3(HH / 128, NN / 128), 256>>>(X, Wkh, K, NN, HH, DD, bkh);

        // row norms
        rownorm_kernel<<<NN, 256>>>(Q, K, qn, kn);

        // gram: A = Q @ K^T
        gemm_nt_kernel<<<dim3(NN / 128, NN / 128), 256>>>(Q, K, A, NN, NN, HH, nullptr);

        // order statistics per row
        select_kernel<<<NN, 256>>>(A, qn, kn, md, kth);

        // affinity + prune + diag (in place)
        aff_kernel<<<(int)(((size_t)NN * NN + 255) / 256), 256>>>(A, qn, kn, md, kth);

        // P = softmax_rows(A + A^T)
        transadd_kernel<<<dim3(NN / 32, NN / 32), dim3(32, 8)>>>(A, P);
        softmax_kernel<<<NN, 256>>>(P);

        // P2 = P @ P
        gemm_nn_kernel<<<dim3(NN / 128, NN / 128), 256>>>(P, P, P2, NN, NN, NN, 1.0f, 0.0f);

        // ctx_h = P2 @ (P2 @ (P2 @ X)) ; out += 0.25 * ctx_h
        gemm_nn_kernel<<<dim3(DD / 128, NN / 128), 256>>>(P2, X, Y, NN, DD, NN, 1.0f, 0.0f);
        gemm_nn_kernel<<<dim3(DD / 128, NN / 128), 256>>>(P2, Y, Y2, NN, DD, NN, 1.0f, 0.0f);
        gemm_nn_kernel<<<dim3(DD / 128, NN / 128), 256>>>(P2, Y2, out, NN, DD, NN, 0.25f, 1.0f);
    }
}

// round 3
// speedup vs baseline: 2.4343x; 2.4343x over previous
#include <cuda_runtime.h>
#include <cuda_bf16.h>
#include <math.h>
#include <float.h>
#include <stdint.h>

#define NN 4096
#define DD 2048
#define HH 256
#define HEADS 4
#define K3DD (3*DD)
#define K3HH (3*HH)
#define K3NN (3*NN)

// ---------------- static device scratch (no cudaMalloc allowed) ----------------
__device__ float g_Q[NN * HH];
__device__ float g_K[NN * HH];
__device__ float g_qn[NN];
__device__ float g_kn[NN];
__device__ float g_md[NN];
__device__ float g_kth[NN];
__device__ float g_A[(size_t)NN * NN];
__device__ float g_P[(size_t)NN * NN];
__device__ float g_P2[(size_t)NN * NN];
__device__ float g_Y[(size_t)NN * DD];
__device__ float g_Y2[(size_t)NN * DD];

__device__ __nv_bfloat16 s_Xa[(size_t)NN * K3DD];   // X  A-layout [h|l|h]
__device__ __nv_bfloat16 s_Wb[(size_t)HH * K3DD];   // W  B-layout [h|h|l]
__device__ __nv_bfloat16 s_Qa[(size_t)NN * K3HH];
__device__ __nv_bfloat16 s_Kb[(size_t)NN * K3HH];
__device__ __nv_bfloat16 s_Pa[(size_t)NN * K3NN];   // P   A-layout
__device__ __nv_bfloat16 s_PtB[(size_t)NN * K3NN];  // P^T B-layout
__device__ __nv_bfloat16 s_P2a[(size_t)NN * K3NN];  // P2  A-layout
__device__ __nv_bfloat16 s_XtB[(size_t)DD * K3NN];  // X^T B-layout
__device__ __nv_bfloat16 s_YtB[(size_t)DD * K3NN];  // Y^T / Y2^T B-layout

// ---------------- mma.sync bf16 NT GEMM ----------------
// C[M,N] = alpha * A[M,K] @ B[N,K]^T + beta*C + bias[n]
// A, B bf16 K-major. M%128==0, N%128==0, K%32==0.
#define BM 128
#define BN 128
#define BK 32
#define STAGES 3
#define PAD_ELE 40              // row stride in bf16 elements (80 bytes)
#define STAGE_BYTES (2 * BM * PAD_ELE * 2)   // A tile + B tile per stage
#define GEMM_SMEM (STAGES * STAGE_BYTES)     // 61440

__device__ __forceinline__ uint32_t smem_u32(const void* p) {
    uint32_t a;
    asm("{ .reg .u64 t; cvta.to.shared.u64 t, %1; cvt.u32.u64 %0, t; }" : "=r"(a) : "l"(p));
    return a;
}
#define CP_ASYNC16(sa, ga) \
    asm volatile("cp.async.cg.shared.global [%0], [%1], 16;" :: "r"(sa), "l"(ga))
#define CP_COMMIT() asm volatile("cp.async.commit_group;" ::: "memory")
#define CP_WAIT1()  asm volatile("cp.async.wait_group 1;" ::: "memory")
#define CP_WAIT0()  asm volatile("cp.async.wait_group 0;" ::: "memory")
#define LDSM_X4(r0, r1, r2, r3, a) \
    asm volatile("ldmatrix.sync.aligned.m8n8.x4.shared.b16 {%0,%1,%2,%3}, [%4];" \
        : "=r"(r0), "=r"(r1), "=r"(r2), "=r"(r3) : "r"(a))
#define MMA16816(c, a0, a1, a2, a3, b0, b1) \
    asm volatile("mma.sync.aligned.m16n8k16.row.col.f32.bf16.bf16.f32 " \
        "{%0,%1,%2,%3}, {%4,%5,%6,%7}, {%8,%9}, {%0,%1,%2,%3};" \
        : "+f"((c)[0]), "+f"((c)[1]), "+f"((c)[2]), "+f"((c)[3]) \
        : "r"(a0), "r"(a1), "r"(a2), "r"(a3), "r"(b0), "r"(b1))

__global__ __launch_bounds__(256, 2) void mma_gemm_nt(
    const __nv_bfloat16* __restrict__ A, const __nv_bfloat16* __restrict__ B,
    float* __restrict__ C, int M, int N, int K, int ldc,
    float alpha, float beta, const float* __restrict__ bias)
{
    extern __shared__ __align__(128) char smem[];
    const uint32_t sbase = smem_u32(smem);
    const int tid = threadIdx.x;
    const int wid = tid >> 5;
    const int lane = tid & 31;
    const int wm = (wid & 1) * 64;   // warp row offset in CTA tile
    const int wn = (wid >> 1) * 32;  // warp col offset in CTA tile

    const int m0 = blockIdx.y * BM;
    const int n0 = blockIdx.x * BN;
    const __nv_bfloat16* gA = A + (size_t)m0 * K;
    const __nv_bfloat16* gB = B + (size_t)n0 * K;

    // per-thread load coords: 512 16B chunks per tile, 2 per thread
    const int lr0 = tid >> 2;            // rows tid/4 and tid/4+64
    const int lc  = (tid & 3) << 3;      // element col: 0,8,16,24

    float acc[4][4][4];
    #pragma unroll
    for (int i = 0; i < 4; i++)
        #pragma unroll
        for (int j = 0; j < 4; j++)
            #pragma unroll
            for (int q = 0; q < 4; q++) acc[i][j][q] = 0.0f;

    const int KT = K / BK;

    // prologue: stage 0 .. STAGES-2
    #pragma unroll
    for (int s = 0; s < STAGES - 1; s++) {
        const int k0 = s * BK;
        uint32_t sa = sbase + s * STAGE_BYTES;
        uint32_t sb = sa + BM * PAD_ELE * 2;
        #pragma unroll
        for (int h = 0; h < 2; h++) {
            int r = lr0 + h * 64;
            CP_ASYNC16(sa + (uint32_t)(r * PAD_ELE + lc) * 2, gA + (size_t)r * K + k0 + lc);
            CP_ASYNC16(sb + (uint32_t)(r * PAD_ELE + lc) * 2, gB + (size_t)r * K + k0 + lc);
        }
        CP_COMMIT();
    }

    // ldmatrix lane addressing
    const int a_row = wm + (lane & 15);          // + mt*16
    const int a_half = (lane >> 4) << 3;         // 0 or 8 (elements)
    const int b_nt2 = (lane >> 4) << 3;          // which of 2 ntiles in x4 (8 rows)
    const int b_half = ((lane >> 3) & 1) << 3;   // k half
    const int b_row = wn + b_nt2 + (lane & 7);   // + group*16

    for (int kt = 0; kt < KT; kt++) {
        CP_WAIT1();
        __syncthreads();

        // issue next tile
        if (kt + STAGES - 1 < KT) {
            const int s = (kt + STAGES - 1) % STAGES;
            const int k0 = (kt + STAGES - 1) * BK;
            uint32_t sa = sbase + s * STAGE_BYTES;
            uint32_t sb = sa + BM * PAD_ELE * 2;
            #pragma unroll
            for (int h = 0; h < 2; h++) {
                int r = lr0 + h * 64;
                CP_ASYNC16(sa + (uint32_t)(r * PAD_ELE + lc) * 2, gA + (size_t)r * K + k0 + lc);
                CP_ASYNC16(sb + (uint32_t)(r * PAD_ELE + lc) * 2, gB + (size_t)r * K + k0 + lc);
            }
        }
        CP_COMMIT();

        const int s = kt % STAGES;
        const uint32_t sa = sbase + s * STAGE_BYTES;
        const uint32_t sb = sa + BM * PAD_ELE * 2;

        #pragma unroll
        for (int kk = 0; kk < 2; kk++) {
            uint32_t a0[4], a1[4], a2[4], a3[4];
            #pragma unroll
            for (int mt = 0; mt < 4; mt++) {
                uint32_t addr = sa + (uint32_t)((a_row + mt * 16) * PAD_ELE + kk * 16 + a_half) * 2;
                LDSM_X4(a0[mt], a1[mt], a2[mt], a3[mt], addr);
            }
            uint32_t b[4][2];
            #pragma unroll
            for (int g = 0; g < 2; g++) {
                uint32_t addr = sb + (uint32_t)((b_row + g * 16) * PAD_ELE + kk * 16 + b_half) * 2;
                uint32_t r0, r1, r2, r3;
                LDSM_X4(r0, r1, r2, r3, addr);
                b[g * 2 + 0][0] = r0; b[g * 2 + 0][1] = r1;
                b[g * 2 + 1][0] = r2; b[g * 2 + 1][1] = r3;
            }
            #pragma unroll
            for (int mt = 0; mt < 4; mt++)
                #pragma unroll
                for (int nt = 0; nt < 4; nt++)
                    MMA16816(acc[mt][nt], a0[mt], a1[mt], a2[mt], a3[mt],
                             b[nt][0], b[nt][1]);
        }
        __syncthreads();
    }
    CP_WAIT0();

    // epilogue
    const int er = lane >> 2;            // 0..7
    const int ec = (lane & 3) << 1;      // 0,2,4,6
    #pragma unroll
    for (int mt = 0; mt < 4; mt++) {
        #pragma unroll
        for (int nt = 0; nt < 4; nt++) {
            int col = n0 + wn + nt * 8 + ec;
            float b0 = bias ? bias[col] : 0.0f;
            float b1 = bias ? bias[col + 1] : 0.0f;
            #pragma unroll
            for (int half = 0; half < 2; half++) {
                int row = m0 + wm + mt * 16 + er + half * 8;
                float* Cp = C + (size_t)row * ldc + col;
                float v0 = alpha * acc[mt][nt][half * 2 + 0] + b0;
                float v1 = alpha * acc[mt][nt][half * 2 + 1] + b1;
                if (beta != 0.0f) { v0 += beta * Cp[0]; v1 += beta * Cp[1]; }
                float2 v = make_float2(v0, v1);
                *(float2*)Cp = v;
            }
        }
    }
}

// ---------------- split fp32 -> bf16 hi/lo, K-concatenated ----------------
// lo_mid=1 (A-layout): [h|l|h]; lo_mid=0 (B-layout): [h|h|l]. dst row stride = 3C.
__global__ void split_kernel(const float* __restrict__ src, __nv_bfloat16* __restrict__ dst,
                             int total, int logC, int lo_mid)
{
    int idx = blockIdx.x * blockDim.x + threadIdx.x;
    if (idx >= total) return;
    int C = 1 << logC;
    int r = idx >> logC;
    int c = idx & (C - 1);
    float x = src[idx];
    __nv_bfloat16 h = __float2bfloat16(x);
    __nv_bfloat16 l = __float2bfloat16(x - __bfloat162float(h));
    size_t base = (size_t)r * 3 * C + c;
    if (lo_mid) { dst[base] = h; dst[base + C] = l; dst[base + 2 * C] = h; }
    else        { dst[base] = h; dst[base + C] = h; dst[base + 2 * C] = l; }
}

// src [R,C] fp32 -> dst [C, 3R] bf16 (transposed), B-layout [h|h|l]
__global__ void split_transpose_kernel(const float* __restrict__ src,
                                       __nv_bfloat16* __restrict__ dst, int R, int C)
{
    __shared__ float t[32][33];
    int c0 = blockIdx.x * 32, r0 = blockIdx.y * 32;
    int tx = threadIdx.x, ty = threadIdx.y;  // (32,8)
    for (int i = ty; i < 32; i += 8)
        t[i][tx] = src[(size_t)(r0 + i) * C + c0 + tx];
    __syncthreads();
    for (int i = ty; i < 32; i += 8) {
        int c = c0 + i;
        int r = r0 + tx;
        float x = t[tx][i];
        __nv_bfloat16 h = __float2bfloat16(x);
        __nv_bfloat16 l = __float2bfloat16(x - __bfloat162float(h));
        size_t base = (size_t)c * 3 * R;
        dst[base + r] = h;
        dst[base + R + r] = h;
        dst[base + 2 * R + r] = l;
    }
}

// ---------------- aux kernels ----------------
__global__ void zero_kernel(float* out, int n) {
    int i = blockIdx.x * blockDim.x + threadIdx.x;
    if (i < n) out[i] = 0.0f;
}

__global__ void rownorm_kernel(const float* __restrict__ Q, const float* __restrict__ K,
                               float* __restrict__ qn, float* __restrict__ kn)
{
    int i = blockIdx.x;
    int tid = threadIdx.x;
    __shared__ float sq[256];
    __shared__ float sk[256];
    float q = Q[(size_t)i * HH + tid];
    float k = K[(size_t)i * HH + tid];
    sq[tid] = q * q;
    sk[tid] = k * k;
    __syncthreads();
    for (int s = 128; s > 0; s >>= 1) {
        if (tid < s) { sq[tid] += sq[tid + s]; sk[tid] += sk[tid + s]; }
        __syncthreads();
    }
    if (tid == 0) { qn[i] = sq[0]; kn[i] = sk[0]; }
}

__global__ void select_kernel(const float* __restrict__ G,
                              const float* __restrict__ qn, const float* __restrict__ kn,
                              float* __restrict__ md_out, float* __restrict__ kth_out)
{
    int i = blockIdx.x;
    int tid = threadIdx.x;
    __shared__ float sd[NN];
    __shared__ float rmin[256];
    __shared__ int ridx[256];
    __shared__ float sel[30];
    float qni = qn[i];
    const float* Gi = G + (size_t)i * NN;
    for (int j = tid; j < NN; j += 256) {
        float sq = qni + kn[j] - 2.0f * Gi[j];
        sd[j] = sqrtf(fmaxf(sq, 0.0f) + 1e-10f);
    }
    __syncthreads();
    for (int it = 0; it < 30; it++) {
        float mv = FLT_MAX;
        int mi = -1;
        for (int j = tid; j < NN; j += 256) {
            float v = sd[j];
            if (v < mv) { mv = v; mi = j; }
        }
        rmin[tid] = mv;
        ridx[tid] = mi;
        __syncthreads();
        for (int s = 128; s > 0; s >>= 1) {
            if (tid < s) {
                float v2 = rmin[tid + s];
                if (v2 < rmin[tid] || (v2 == rmin[tid] && ridx[tid + s] < ridx[tid])) {
                    rmin[tid] = v2;
                    ridx[tid] = ridx[tid + s];
                }
            }
            __syncthreads();
        }
        if (tid == 0) {
            sel[it] = rmin[0];
            sd[ridx[0]] = FLT_MAX;
        }
        __syncthreads();
    }
    if (tid == 0) {
        float mdp = sel[10] + 1e-10f;
        float t = sel[29] / mdp;
        md_out[i] = mdp;
        kth_out[i] = expf(-(t * t));
    }
}

__global__ void aff_kernel(float* __restrict__ A,
                           const float* __restrict__ qn, const float* __restrict__ kn,
                           const float* __restrict__ mdp, const float* __restrict__ kth)
{
    size_t idx = (size_t)blockIdx.x * blockDim.x + threadIdx.x;
    if (idx >= (size_t)NN * NN) return;
    int i = (int)(idx >> 12);
    int j = (int)(idx & 4095);
    float sq = qn[i] + kn[j] - 2.0f * A[idx];
    float d = sqrtf(fmaxf(sq, 0.0f) + 1e-10f);
    float dd = d / mdp[i];
    float a = expf(-(dd * dd));
    float r = (a >= kth[i]) ? a : 0.0f;
    if (j == i) r = 1.0f;
    A[idx] = r;
}

__global__ void transadd_kernel(const float* __restrict__ A, float* __restrict__ B)
{
    __shared__ float tile[32][33];
    int x0 = blockIdx.x * 32;
    int y0 = blockIdx.y * 32;
    int tx = threadIdx.x;
    int ty = threadIdx.y;
    for (int r = ty; r < 32; r += 8)
        tile[r][tx] = A[(size_t)(x0 + r) * NN + y0 + tx];
    __syncthreads();
    for (int r = ty; r < 32; r += 8) {
        size_t idx = (size_t)(y0 + r) * NN + x0 + tx;
        B[idx] = A[idx] + tile[tx][r];
    }
}

__global__ void softmax_kernel(float* __restrict__ P)
{
    int i = blockIdx.x;
    int tid = threadIdx.x;
    __shared__ float s[NN];
    __shared__ float red[256];
    size_t base = (size_t)i * NN;
    float m = -FLT_MAX;
    for (int j = tid; j < NN; j += 256) {
        float v = P[base + j];
        s[j] = v;
        m = fmaxf(m, v);
    }
    red[tid] = m;
    __syncthreads();
    for (int st = 128; st > 0; st >>= 1) {
        if (tid < st) red[tid] = fmaxf(red[tid], red[tid + st]);
        __syncthreads();
    }
    m = red[0];
    __syncthreads();
    float sum = 0.0f;
    for (int j = tid; j < NN; j += 256) {
        float e = expf(s[j] - m);
        s[j] = e;
        sum += e;
    }
    red[tid] = sum;
    __syncthreads();
    for (int st = 128; st > 0; st >>= 1) {
        if (tid < st) red[tid] += red[tid + st];
        __syncthreads();
    }
    float inv = 1.0f / red[0];
    for (int j = tid; j < NN; j += 256)
        P[base + j] = s[j] * inv;
}

// ---------------- launch ----------------
static void run_gemm(const __nv_bfloat16* A, const __nv_bfloat16* B, float* C,
                     int M, int N, int K, int ldc, float alpha, float beta,
                     const float* bias)
{
    dim3 grid(N / BN, M / BM);
    mma_gemm_nt<<<grid, 256, GEMM_SMEM>>>(A, B, C, M, N, K, ldc, alpha, beta, bias);
}

extern "C" void kernel_launch(void* const* d_in, const int* in_sizes, int n_in,
                              void* d_out, int out_size)
{
    const float* X  = (const float*)d_in[0];
    const float* Wq = (const float*)d_in[1];
    const float* bq = (const float*)d_in[2];
    const float* Wk = (const float*)d_in[3];
    const float* bk = (const float*)d_in[4];
    float* out = (float*)d_out;

    static int smem_set = 0;
    if (!smem_set) {
        cudaFuncSetAttribute(mma_gemm_nt, cudaFuncAttributeMaxDynamicSharedMemorySize,
                             GEMM_SMEM);
        smem_set = 1;
    }

    float *Q, *K, *qn, *kn, *md, *kth, *A, *P, *P2, *Y, *Y2;
    __nv_bfloat16 *Xa, *Wb, *Qa, *Kb, *Pa, *PtB, *P2a, *XtB, *YtB;
    cudaGetSymbolAddress((void**)&Q,  g_Q);
    cudaGetSymbolAddress((void**)&K,  g_K);
    cudaGetSymbolAddress((void**)&qn, g_qn);
    cudaGetSymbolAddress((void**)&kn, g_kn);
    cudaGetSymbolAddress((void**)&md, g_md);
    cudaGetSymbolAddress((void**)&kth, g_kth);
    cudaGetSymbolAddress((void**)&A,  g_A);
    cudaGetSymbolAddress((void**)&P,  g_P);
    cudaGetSymbolAddress((void**)&P2, g_P2);
    cudaGetSymbolAddress((void**)&Y,  g_Y);
    cudaGetSymbolAddress((void**)&Y2, g_Y2);
    cudaGetSymbolAddress((void**)&Xa,  s_Xa);
    cudaGetSymbolAddress((void**)&Wb,  s_Wb);
    cudaGetSymbolAddress((void**)&Qa,  s_Qa);
    cudaGetSymbolAddress((void**)&Kb,  s_Kb);
    cudaGetSymbolAddress((void**)&Pa,  s_Pa);
    cudaGetSymbolAddress((void**)&PtB, s_PtB);
    cudaGetSymbolAddress((void**)&P2a, s_P2a);
    cudaGetSymbolAddress((void**)&XtB, s_XtB);
    cudaGetSymbolAddress((void**)&YtB, s_YtB);

    zero_kernel<<<(NN * DD + 255) / 256, 256>>>(out, NN * DD);

    // X once: A-layout and transposed B-layout
    split_kernel<<<(NN * DD + 255) / 256, 256>>>(X, Xa, NN * DD, 11, 1);
    split_transpose_kernel<<<dim3(DD / 32, NN / 32), dim3(32, 8)>>>(X, XtB, NN, DD);

    for (int h = 0; h < HEADS; h++) {
        const float* Wqh = Wq + (size_t)h * HH * DD;
        const float* Wkh = Wk + (size_t)h * HH * DD;
        const float* bqh = bq + (size_t)h * HH;
        const float* bkh = bk + (size_t)h * HH;

        // Q = X @ Wq^T + bq ; K = X @ Wk^T + bk
        split_kernel<<<(HH * DD + 255) / 256, 256>>>(Wqh, Wb, HH * DD, 11, 0);
        run_gemm(Xa, Wb, Q, NN, HH, K3DD, HH, 1.0f, 0.0f, bqh);
        split_kernel<<<(HH * DD + 255) / 256, 256>>>(Wkh, Wb, HH * DD, 11, 0);
        run_gemm(Xa, Wb, K, NN, HH, K3DD, HH, 1.0f, 0.0f, bkh);

        rownorm_kernel<<<NN, 256>>>(Q, K, qn, kn);

        // gram = Q @ K^T
        split_kernel<<<(NN * HH + 255) / 256, 256>>>(Q, Qa, NN * HH, 8, 1);
        split_kernel<<<(NN * HH + 255) / 256, 256>>>(K, Kb, NN * HH, 8, 0);
        run_gemm(Qa, Kb, A, NN, NN, K3HH, NN, 1.0f, 0.0f, nullptr);

        select_kernel<<<NN, 256>>>(A, qn, kn, md, kth);
        aff_kernel<<<(int)(((size_t)NN * NN + 255) / 256), 256>>>(A, qn, kn, md, kth);
        transadd_kernel<<<dim3(NN / 32, NN / 32), dim3(32, 8)>>>(A, P);
        softmax_kernel<<<NN, 256>>>(P);

        // P2 = P @ P
        split_kernel<<<(int)(((size_t)NN * NN + 255) / 256), 256>>>(P, Pa, NN * NN, 12, 1);
        split_transpose_kernel<<<dim3(NN / 32, NN / 32), dim3(32, 8)>>>(P, PtB, NN, NN);
        run_gemm(Pa, PtB, P2, NN, NN, K3NN, NN, 1.0f, 0.0f, nullptr);

        // ctx = P2 @ (P2 @ (P2 @ X)); out += 0.25 * ctx
        split_kernel<<<(int)(((size_t)NN * NN + 255) / 256), 256>>>(P2, P2a, NN * NN, 12, 1);
        run_gemm(P2a, XtB, Y, NN, DD, K3NN, DD, 1.0f, 0.0f, nullptr);
        split_transpose_kernel<<<dim3(DD / 32, NN / 32), dim3(32, 8)>>>(Y, YtB, NN, DD);
        run_gemm(P2a, YtB, Y2, NN, DD, K3NN, DD, 1.0f, 0.0f, nullptr);
        split_transpose_kernel<<<dim3(DD / 32, NN / 32), dim3(32, 8)>>>(Y2, YtB, NN, DD);
        run_gemm(P2a, YtB, out, NN, DD, K3NN, DD, 0.25f, 1.0f, nullptr);
    }
}

// round 4
// speedup vs baseline: 2.8456x; 1.1690x over previous
#include <cuda_runtime.h>
#include <cuda_bf16.h>
#include <cuda_fp16.h>
#include <math.h>
#include <float.h>
#include <stdint.h>

#define NN 4096
#define DD 2048
#define HH 256
#define HEADS 4
#define K3DD (3*DD)
#define K3HH (3*HH)
#define K2NN (2*NN)

#define SCALE_P 1024.0f
#define SCALE_Y 32.0f

// ---------------- static device scratch (no cudaMalloc allowed) ----------------
__device__ float g_Q[NN * HH];
__device__ float g_K[NN * HH];
__device__ float g_qn[NN];
__device__ float g_kn[NN];
__device__ float g_md[NN];
__device__ float g_kth[NN];
__device__ float g_A[(size_t)NN * NN];
__device__ float g_P[(size_t)NN * NN];
__device__ float g_Y[(size_t)NN * DD];
__device__ float g_Y2[(size_t)NN * DD];

__device__ __nv_bfloat16 s_Xa[(size_t)NN * K3DD];   // X  A-layout [h|l|h] (bf16 3-term)
__device__ __nv_bfloat16 s_Wb[(size_t)HH * K3DD];   // Wq B-layout [h|h|l]
__device__ __nv_bfloat16 s_Wb2[(size_t)HH * K3DD];  // Wk B-layout
__device__ __nv_bfloat16 s_Qa[(size_t)NN * K3HH];
__device__ __nv_bfloat16 s_Kb[(size_t)NN * K3HH];

__device__ __half f_Pa[(size_t)NN * K2NN];          // scaled P, A-layout [h|l] fp16
__device__ __half f_XtB[(size_t)DD * K2NN];         // X^T B-layout [h|h] fp16
__device__ __half f_YtB[(size_t)DD * K2NN];         // Y^T B-layout [h|h] fp16

// ---------------- mma.sync NT GEMM (templated bf16 / fp16) ----------------
// C[M,N] = alpha * A[M,K] @ B[N,K]^T + beta*C + bias[n]
#define BM 128
#define BN 128
#define BK 32
#define STAGES 3
#define PAD_ELE 40
#define STAGE_BYTES (2 * BM * PAD_ELE * 2)
#define GEMM_SMEM (STAGES * STAGE_BYTES)

__device__ __forceinline__ uint32_t smem_u32(const void* p) {
    uint32_t a;
    asm("{ .reg .u64 t; cvta.to.shared.u64 t, %1; cvt.u32.u64 %0, t; }" : "=r"(a) : "l"(p));
    return a;
}
#define CP_ASYNC16(sa, ga) \
    asm volatile("cp.async.cg.shared.global [%0], [%1], 16;" :: "r"(sa), "l"(ga))
#define CP_COMMIT() asm volatile("cp.async.commit_group;" ::: "memory")
#define CP_WAIT1()  asm volatile("cp.async.wait_group 1;" ::: "memory")
#define CP_WAIT0()  asm volatile("cp.async.wait_group 0;" ::: "memory")
#define LDSM_X4(r0, r1, r2, r3, a) \
    asm volatile("ldmatrix.sync.aligned.m8n8.x4.shared.b16 {%0,%1,%2,%3}, [%4];" \
        : "=r"(r0), "=r"(r1), "=r"(r2), "=r"(r3) : "r"(a))

__device__ __forceinline__ void mma16816(float* c, uint32_t a0, uint32_t a1,
    uint32_t a2, uint32_t a3, uint32_t b0, uint32_t b1, __nv_bfloat16) {
    asm volatile("mma.sync.aligned.m16n8k16.row.col.f32.bf16.bf16.f32 "
        "{%0,%1,%2,%3}, {%4,%5,%6,%7}, {%8,%9}, {%0,%1,%2,%3};"
        : "+f"(c[0]), "+f"(c[1]), "+f"(c[2]), "+f"(c[3])
        : "r"(a0), "r"(a1), "r"(a2), "r"(a3), "r"(b0), "r"(b1));
}
__device__ __forceinline__ void mma16816(float* c, uint32_t a0, uint32_t a1,
    uint32_t a2, uint32_t a3, uint32_t b0, uint32_t b1, __half) {
    asm volatile("mma.sync.aligned.m16n8k16.row.col.f32.f16.f16.f32 "
        "{%0,%1,%2,%3}, {%4,%5,%6,%7}, {%8,%9}, {%0,%1,%2,%3};"
        : "+f"(c[0]), "+f"(c[1]), "+f"(c[2]), "+f"(c[3])
        : "r"(a0), "r"(a1), "r"(a2), "r"(a3), "r"(b0), "r"(b1));
}

template<typename T>
__global__ __launch_bounds__(256, 2) void mma_gemm_nt(
    const T* __restrict__ A, const T* __restrict__ B,
    float* __restrict__ C, int M, int N, int K, int ldc,
    float alpha, float beta, const float* __restrict__ bias)
{
    extern __shared__ __align__(128) char smem[];
    const uint32_t sbase = smem_u32(smem);
    const int tid = threadIdx.x;
    const int wid = tid >> 5;
    const int lane = tid & 31;
    const int wm = (wid & 1) * 64;
    const int wn = (wid >> 1) * 32;

    // grid swizzle: 8-row supergroups for L2 reuse (gridDim.y is a multiple of 8 here)
    const int nbx = gridDim.x;
    int id = blockIdx.y * nbx + blockIdx.x;
    int grp = id / (8 * nbx);
    int rem = id - grp * (8 * nbx);
    const int m0 = (grp * 8 + (rem & 7)) * BM;
    const int n0 = (rem >> 3) * BN;

    const T* gA = A + (size_t)m0 * K;
    const T* gB = B + (size_t)n0 * K;

    const int lr0 = tid >> 2;
    const int lc  = (tid & 3) << 3;

    float acc[4][4][4];
    #pragma unroll
    for (int i = 0; i < 4; i++)
        #pragma unroll
        for (int j = 0; j < 4; j++)
            #pragma unroll
            for (int q = 0; q < 4; q++) acc[i][j][q] = 0.0f;

    const int KT = K / BK;

    #pragma unroll
    for (int s = 0; s < STAGES - 1; s++) {
        const int k0 = s * BK;
        uint32_t sa = sbase + s * STAGE_BYTES;
        uint32_t sb = sa + BM * PAD_ELE * 2;
        #pragma unroll
        for (int h = 0; h < 2; h++) {
            int r = lr0 + h * 64;
            CP_ASYNC16(sa + (uint32_t)(r * PAD_ELE + lc) * 2, gA + (size_t)r * K + k0 + lc);
            CP_ASYNC16(sb + (uint32_t)(r * PAD_ELE + lc) * 2, gB + (size_t)r * K + k0 + lc);
        }
        CP_COMMIT();
    }

    const int a_row = wm + (lane & 15);
    const int a_half = (lane >> 4) << 3;
    const int b_nt2 = (lane >> 4) << 3;
    const int b_half = ((lane >> 3) & 1) << 3;
    const int b_row = wn + b_nt2 + (lane & 7);

    for (int kt = 0; kt < KT; kt++) {
        CP_WAIT1();
        __syncthreads();

        if (kt + STAGES - 1 < KT) {
            const int s = (kt + STAGES - 1) % STAGES;
            const int k0 = (kt + STAGES - 1) * BK;
            uint32_t sa = sbase + s * STAGE_BYTES;
            uint32_t sb = sa + BM * PAD_ELE * 2;
            #pragma unroll
            for (int h = 0; h < 2; h++) {
                int r = lr0 + h * 64;
                CP_ASYNC16(sa + (uint32_t)(r * PAD_ELE + lc) * 2, gA + (size_t)r * K + k0 + lc);
                CP_ASYNC16(sb + (uint32_t)(r * PAD_ELE + lc) * 2, gB + (size_t)r * K + k0 + lc);
            }
        }
        CP_COMMIT();

        const int s = kt % STAGES;
        const uint32_t sa = sbase + s * STAGE_BYTES;
        const uint32_t sb = sa + BM * PAD_ELE * 2;

        #pragma unroll
        for (int kk = 0; kk < 2; kk++) {
            uint32_t a0[4], a1[4], a2[4], a3[4];
            #pragma unroll
            for (int mt = 0; mt < 4; mt++) {
                uint32_t addr = sa + (uint32_t)((a_row + mt * 16) * PAD_ELE + kk * 16 + a_half) * 2;
                LDSM_X4(a0[mt], a1[mt], a2[mt], a3[mt], addr);
            }
            uint32_t b[4][2];
            #pragma unroll
            for (int g = 0; g < 2; g++) {
                uint32_t addr = sb + (uint32_t)((b_row + g * 16) * PAD_ELE + kk * 16 + b_half) * 2;
                uint32_t r0, r1, r2, r3;
                LDSM_X4(r0, r1, r2, r3, addr);
                b[g * 2 + 0][0] = r0; b[g * 2 + 0][1] = r1;
                b[g * 2 + 1][0] = r2; b[g * 2 + 1][1] = r3;
            }
            #pragma unroll
            for (int mt = 0; mt < 4; mt++)
                #pragma unroll
                for (int nt = 0; nt < 4; nt++)
                    mma16816(acc[mt][nt], a0[mt], a1[mt], a2[mt], a3[mt],
                             b[nt][0], b[nt][1], T{});
        }
        __syncthreads();
    }
    CP_WAIT0();

    const int er = lane >> 2;
    const int ec = (lane & 3) << 1;
    #pragma unroll
    for (int mt = 0; mt < 4; mt++) {
        #pragma unroll
        for (int nt = 0; nt < 4; nt++) {
            int col = n0 + wn + nt * 8 + ec;
            float b0 = bias ? bias[col] : 0.0f;
            float b1 = bias ? bias[col + 1] : 0.0f;
            #pragma unroll
            for (int half = 0; half < 2; half++) {
                int row = m0 + wm + mt * 16 + er + half * 8;
                float* Cp = C + (size_t)row * ldc + col;
                float v0 = alpha * acc[mt][nt][half * 2 + 0] + b0;
                float v1 = alpha * acc[mt][nt][half * 2 + 1] + b1;
                if (beta != 0.0f) { v0 += beta * Cp[0]; v1 += beta * Cp[1]; }
                float2 v = make_float2(v0, v1);
                *(float2*)Cp = v;
            }
        }
    }
}

// ---------------- bf16 3-term splits (proj/gram path) ----------------
__global__ void split_kernel(const float* __restrict__ src, __nv_bfloat16* __restrict__ dst,
                             int total, int logC, int lo_mid)
{
    int idx = blockIdx.x * blockDim.x + threadIdx.x;
    if (idx >= total) return;
    int C = 1 << logC;
    int r = idx >> logC;
    int c = idx & (C - 1);
    float x = src[idx];
    __nv_bfloat16 h = __float2bfloat16(x);
    __nv_bfloat16 l = __float2bfloat16(x - __bfloat162float(h));
    size_t base = (size_t)r * 3 * C + c;
    if (lo_mid) { dst[base] = h; dst[base + C] = l; dst[base + 2 * C] = h; }
    else        { dst[base] = h; dst[base + C] = h; dst[base + 2 * C] = l; }
}

// ---------------- fp16 2-term A-layout split: dst[r] = [h | l], scaled ----------------
__global__ void split2_f16(const float* __restrict__ src, __half* __restrict__ dst,
                           int total, int logC, float scale)
{
    int idx = blockIdx.x * blockDim.x + threadIdx.x;
    if (idx >= total) return;
    int C = 1 << logC;
    int r = idx >> logC;
    int c = idx & (C - 1);
    float x = src[idx] * scale;
    __half h = __float2half(x);
    __half l = __float2half(x - __half2float(h));
    size_t base = (size_t)r * 2 * C + c;
    dst[base] = h;
    dst[base + C] = l;
}

// ---------------- fp16 transpose + hi-dup B-layout: src[R,C] -> dst[C, 2R] ----------------
__global__ void split1t_f16(const float* __restrict__ src, __half* __restrict__ dst,
                            int R, int C, float scale)
{
    __shared__ float t[32][33];
    int c0 = blockIdx.x * 32, r0 = blockIdx.y * 32;
    int tx = threadIdx.x, ty = threadIdx.y;
    for (int i = ty; i < 32; i += 8)
        t[i][tx] = src[(size_t)(r0 + i) * C + c0 + tx];
    __syncthreads();
    for (int i = ty; i < 32; i += 8) {
        int c = c0 + i;
        int r = r0 + tx;
        __half h = __float2half(t[tx][i] * scale);
        size_t base = (size_t)c * 2 * R;
        dst[base + r] = h;
        dst[base + R + r] = h;
    }
}

// ---------------- aux kernels ----------------
__global__ void zero_kernel(float* out, int n) {
    int i = blockIdx.x * blockDim.x + threadIdx.x;
    if (i < n) out[i] = 0.0f;
}

__global__ void rownorm_kernel(const float* __restrict__ Q, const float* __restrict__ K,
                               float* __restrict__ qn, float* __restrict__ kn)
{
    int i = blockIdx.x;
    int tid = threadIdx.x;
    __shared__ float sq[256];
    __shared__ float sk[256];
    float q = Q[(size_t)i * HH + tid];
    float k = K[(size_t)i * HH + tid];
    sq[tid] = q * q;
    sk[tid] = k * k;
    __syncthreads();
    for (int s = 128; s > 0; s >>= 1) {
        if (tid < s) { sq[tid] += sq[tid + s]; sk[tid] += sk[tid + s]; }
        __syncthreads();
    }
    if (tid == 0) { qn[i] = sq[0]; kn[i] = sk[0]; }
}

__global__ void select_kernel(const float* __restrict__ G,
                              const float* __restrict__ qn, const float* __restrict__ kn,
                              float* __restrict__ md_out, float* __restrict__ kth_out)
{
    int i = blockIdx.x;
    int tid = threadIdx.x;
    __shared__ float sd[NN];
    __shared__ float rmin[256];
    __shared__ int ridx[256];
    __shared__ float sel[30];
    float qni = qn[i];
    const float* Gi = G + (size_t)i * NN;
    for (int j = tid; j < NN; j += 256) {
        float sq = qni + kn[j] - 2.0f * Gi[j];
        sd[j] = sqrtf(fmaxf(sq, 0.0f) + 1e-10f);
    }
    __syncthreads();
    for (int it = 0; it < 30; it++) {
        float mv = FLT_MAX;
        int mi = -1;
        for (int j = tid; j < NN; j += 256) {
            float v = sd[j];
            if (v < mv) { mv = v; mi = j; }
        }
        rmin[tid] = mv;
        ridx[tid] = mi;
        __syncthreads();
        for (int s = 128; s > 0; s >>= 1) {
            if (tid < s) {
                float v2 = rmin[tid + s];
                if (v2 < rmin[tid] || (v2 == rmin[tid] && ridx[tid + s] < ridx[tid])) {
                    rmin[tid] = v2;
                    ridx[tid] = ridx[tid + s];
                }
            }
            __syncthreads();
        }
        if (tid == 0) {
            sel[it] = rmin[0];
            sd[ridx[0]] = FLT_MAX;
        }
        __syncthreads();
    }
    if (tid == 0) {
        float mdp = sel[10] + 1e-10f;
        float t = sel[29] / mdp;
        md_out[i] = mdp;
        kth_out[i] = expf(-(t * t));
    }
}

__global__ void aff_kernel(float* __restrict__ A,
                           const float* __restrict__ qn, const float* __restrict__ kn,
                           const float* __restrict__ mdp, const float* __restrict__ kth)
{
    size_t idx = (size_t)blockIdx.x * blockDim.x + threadIdx.x;
    if (idx >= (size_t)NN * NN) return;
    int i = (int)(idx >> 12);
    int j = (int)(idx & 4095);
    float sq = qn[i] + kn[j] - 2.0f * A[idx];
    float d = sqrtf(fmaxf(sq, 0.0f) + 1e-10f);
    float dd = d / mdp[i];
    float a = expf(-(dd * dd));
    float r = (a >= kth[i]) ? a : 0.0f;
    if (j == i) r = 1.0f;
    A[idx] = r;
}

__global__ void transadd_kernel(const float* __restrict__ A, float* __restrict__ B)
{
    __shared__ float tile[32][33];
    int x0 = blockIdx.x * 32;
    int y0 = blockIdx.y * 32;
    int tx = threadIdx.x;
    int ty = threadIdx.y;
    for (int r = ty; r < 32; r += 8)
        tile[r][tx] = A[(size_t)(x0 + r) * NN + y0 + tx];
    __syncthreads();
    for (int r = ty; r < 32; r += 8) {
        size_t idx = (size_t)(y0 + r) * NN + x0 + tx;
        B[idx] = A[idx] + tile[tx][r];
    }
}

__global__ void softmax_kernel(float* __restrict__ P)
{
    int i = blockIdx.x;
    int tid = threadIdx.x;
    __shared__ float s[NN];
    __shared__ float red[256];
    size_t base = (size_t)i * NN;
    float m = -FLT_MAX;
    for (int j = tid; j < NN; j += 256) {
        float v = P[base + j];
        s[j] = v;
        m = fmaxf(m, v);
    }
    red[tid] = m;
    __syncthreads();
    for (int st = 128; st > 0; st >>= 1) {
        if (tid < st) red[tid] = fmaxf(red[tid], red[tid + st]);
        __syncthreads();
    }
    m = red[0];
    __syncthreads();
    float sum = 0.0f;
    for (int j = tid; j < NN; j += 256) {
        float e = expf(s[j] - m);
        s[j] = e;
        sum += e;
    }
    red[tid] = sum;
    __syncthreads();
    for (int st = 128; st > 0; st >>= 1) {
        if (tid < st) red[tid] += red[tid + st];
        __syncthreads();
    }
    float inv = 1.0f / red[0];
    for (int j = tid; j < NN; j += 256)
        P[base + j] = s[j] * inv;
}

// ---------------- launch ----------------
template<typename T>
static void run_gemm(const T* A, const T* B, float* C, int M, int N, int K, int ldc,
                     float alpha, float beta, const float* bias)
{
    dim3 grid(N / BN, M / BM);
    mma_gemm_nt<T><<<grid, 256, GEMM_SMEM>>>(A, B, C, M, N, K, ldc, alpha, beta, bias);
}

extern "C" void kernel_launch(void* const* d_in, const int* in_sizes, int n_in,
                              void* d_out, int out_size)
{
    const float* X  = (const float*)d_in[0];
    const float* Wq = (const float*)d_in[1];
    const float* bq = (const float*)d_in[2];
    const float* Wk = (const float*)d_in[3];
    const float* bk = (const float*)d_in[4];
    float* out = (float*)d_out;

    static int smem_set = 0;
    if (!smem_set) {
        cudaFuncSetAttribute(mma_gemm_nt<__nv_bfloat16>,
                             cudaFuncAttributeMaxDynamicSharedMemorySize, GEMM_SMEM);
        cudaFuncSetAttribute(mma_gemm_nt<__half>,
                             cudaFuncAttributeMaxDynamicSharedMemorySize, GEMM_SMEM);
        smem_set = 1;
    }

    float *Q, *K, *qn, *kn, *md, *kth, *A, *P, *Y, *Y2;
    __nv_bfloat16 *Xa, *Wb, *Wb2, *Qa, *Kb;
    __half *Pa, *XtB, *YtB;
    cudaGetSymbolAddress((void**)&Q,  g_Q);
    cudaGetSymbolAddress((void**)&K,  g_K);
    cudaGetSymbolAddress((void**)&qn, g_qn);
    cudaGetSymbolAddress((void**)&kn, g_kn);
    cudaGetSymbolAddress((void**)&md, g_md);
    cudaGetSymbolAddress((void**)&kth, g_kth);
    cudaGetSymbolAddress((void**)&A,  g_A);
    cudaGetSymbolAddress((void**)&P,  g_P);
    cudaGetSymbolAddress((void**)&Y,  g_Y);
    cudaGetSymbolAddress((void**)&Y2, g_Y2);
    cudaGetSymbolAddress((void**)&Xa,  s_Xa);
    cudaGetSymbolAddress((void**)&Wb,  s_Wb);
    cudaGetSymbolAddress((void**)&Wb2, s_Wb2);
    cudaGetSymbolAddress((void**)&Qa,  s_Qa);
    cudaGetSymbolAddress((void**)&Kb,  s_Kb);
    cudaGetSymbolAddress((void**)&Pa,  f_Pa);
    cudaGetSymbolAddress((void**)&XtB, f_XtB);
    cudaGetSymbolAddress((void**)&YtB, f_YtB);

    const float invP  = 1.0f / SCALE_P;
    const float invPY = 1.0f / (SCALE_P * SCALE_Y);

    // launch order arranged so the 6th launch is a GEMM (for ncu -s 5 -c 1)
    split_kernel<<<(NN * DD + 255) / 256, 256>>>(X, Xa, NN * DD, 11, 1);
    split1t_f16<<<dim3(DD / 32, NN / 32), dim3(32, 8)>>>(X, XtB, NN, DD, 1.0f);
    split_kernel<<<(HH * DD + 255) / 256, 256>>>(Wq, Wb, HH * DD, 11, 0);
    split_kernel<<<(HH * DD + 255) / 256, 256>>>(Wk, Wb2, HH * DD, 11, 0);
    zero_kernel<<<(NN * DD + 255) / 256, 256>>>(out, NN * DD);

    for (int h = 0; h < HEADS; h++) {
        const float* bqh = bq + (size_t)h * HH;
        const float* bkh = bk + (size_t)h * HH;
        if (h > 0) {
            split_kernel<<<(HH * DD + 255) / 256, 256>>>(Wq + (size_t)h * HH * DD, Wb,  HH * DD, 11, 0);
            split_kernel<<<(HH * DD + 255) / 256, 256>>>(Wk + (size_t)h * HH * DD, Wb2, HH * DD, 11, 0);
        }

        // Q = X @ Wq^T + bq ; K = X @ Wk^T + bk  (bf16 3-term)
        run_gemm(Xa, Wb,  Q, NN, HH, K3DD, HH, 1.0f, 0.0f, bqh);
        run_gemm(Xa, Wb2, K, NN, HH, K3DD, HH, 1.0f, 0.0f, bkh);

        rownorm_kernel<<<NN, 256>>>(Q, K, qn, kn);

        // gram = Q @ K^T (bf16 3-term)
        split_kernel<<<(NN * HH + 255) / 256, 256>>>(Q, Qa, NN * HH, 8, 1);
        split_kernel<<<(NN * HH + 255) / 256, 256>>>(K, Kb, NN * HH, 8, 0);
        run_gemm(Qa, Kb, A, NN, NN, K3HH, NN, 1.0f, 0.0f, nullptr);

        select_kernel<<<NN, 256>>>(A, qn, kn, md, kth);
        aff_kernel<<<(int)(((size_t)NN * NN + 255) / 256), 256>>>(A, qn, kn, md, kth);
        transadd_kernel<<<dim3(NN / 32, NN / 32), dim3(32, 8)>>>(A, P);
        softmax_kernel<<<NN, 256>>>(P);

        // split P once (fp16 2-term, scaled); apply P six times to X
        split2_f16<<<(int)(((size_t)NN * NN + 255) / 256), 256>>>(P, Pa, NN * NN, 12, SCALE_P);

        // a1: Y = P @ X
        run_gemm(Pa, XtB, Y, NN, DD, K2NN, DD, invP, 0.0f, nullptr);
        // a2: Y2 = P @ Y
        split1t_f16<<<dim3(DD / 32, NN / 32), dim3(32, 8)>>>(Y, YtB, NN, DD, SCALE_Y);
        run_gemm(Pa, YtB, Y2, NN, DD, K2NN, DD, invPY, 0.0f, nullptr);
        // a3: Y = P @ Y2
        split1t_f16<<<dim3(DD / 32, NN / 32), dim3(32, 8)>>>(Y2, YtB, NN, DD, SCALE_Y);
        run_gemm(Pa, YtB, Y, NN, DD, K2NN, DD, invPY, 0.0f, nullptr);
        // a4: Y2 = P @ Y
        split1t_f16<<<dim3(DD / 32, NN / 32), dim3(32, 8)>>>(Y, YtB, NN, DD, SCALE_Y);
        run_gemm(Pa, YtB, Y2, NN, DD, K2NN, DD, invPY, 0.0f, nullptr);
        // a5: Y = P @ Y2
        split1t_f16<<<dim3(DD / 32, NN / 32), dim3(32, 8)>>>(Y2, YtB, NN, DD, SCALE_Y);
        run_gemm(Pa, YtB, Y, NN, DD, K2NN, DD, invPY, 0.0f, nullptr);
        // a6: out += 0.25 * P @ Y
        split1t_f16<<<dim3(DD / 32, NN / 32), dim3(32, 8)>>>(Y, YtB, NN, DD, SCALE_Y);
        run_gemm(Pa, YtB, out, NN, DD, K2NN, DD, 0.25f * invPY, 1.0f, nullptr);
    }
}

// round 5
// speedup vs baseline: 3.2106x; 1.1283x over previous
#include <cuda_runtime.h>
#include <cuda_bf16.h>
#include <cuda_fp16.h>
#include <math.h>
#include <float.h>
#include <stdint.h>

#define NN 4096
#define DD 2048
#define HH 256
#define HEADS 4
#define K3DD (3*DD)
#define K3HH (3*HH)
#define K2NN (2*NN)
#define NQK 2048      // combined projection output cols (4 heads x 256 x {q,k})

#define SCALE_P 1024.0f
#define SCALE_Y 32.0f

// ---------------- static device scratch ----------------
__device__ float g_QK[(size_t)NN * NQK];   // [Q_h0|..|Q_h3|K_h0|..|K_h3]
__device__ float g_bias[NQK];
__device__ float g_qn[NN];
__device__ float g_kn[NN];
__device__ float g_md[NN];
__device__ float g_kth[NN];
__device__ float g_A[(size_t)NN * NN];
__device__ float g_P[(size_t)NN * NN];
__device__ float g_Y[(size_t)NN * DD];
__device__ float g_Y2[(size_t)NN * DD];

__device__ __nv_bfloat16 s_Xa[(size_t)NN * K3DD];     // X A-layout [h|l|h]
__device__ __nv_bfloat16 s_Wall[(size_t)NQK * K3DD];  // Wq||Wk B-layout [h|h|l]
__device__ __nv_bfloat16 s_Qa[(size_t)NN * K3HH];
__device__ __nv_bfloat16 s_Kb[(size_t)NN * K3HH];

__device__ __half f_Pa[(size_t)NN * K2NN];            // scaled P A-layout [h|l]
__device__ __half f_XtB[(size_t)DD * K2NN];           // X^T B-layout [h|h]
__device__ __half f_YtB[(size_t)DD * K2NN];

// ---------------- mma.sync NT GEMM: 128x256 CTA, 64x64 warp, BK=64 ----------------
#define BM 128
#define BN 256
#define BK 64
#define STAGES 3
#define PAD 72                      // elements per row slot (144 B)
#define A_STAGE (BM * PAD * 2)      // 18432
#define B_STAGE (BN * PAD * 2)      // 36864
#define STAGE_BYTES (A_STAGE + B_STAGE)
#define GEMM_SMEM (STAGES * STAGE_BYTES)   // 165888

__device__ __forceinline__ uint32_t smem_u32(const void* p) {
    uint32_t a;
    asm("{ .reg .u64 t; cvta.to.shared.u64 t, %1; cvt.u32.u64 %0, t; }" : "=r"(a) : "l"(p));
    return a;
}
#define CP_ASYNC16(sa, ga) \
    asm volatile("cp.async.cg.shared.global [%0], [%1], 16;" :: "r"(sa), "l"(ga))
#define CP_COMMIT() asm volatile("cp.async.commit_group;" ::: "memory")
#define CP_WAIT1()  asm volatile("cp.async.wait_group 1;" ::: "memory")
#define CP_WAIT0()  asm volatile("cp.async.wait_group 0;" ::: "memory")
#define LDSM_X4(r0, r1, r2, r3, a) \
    asm volatile("ldmatrix.sync.aligned.m8n8.x4.shared.b16 {%0,%1,%2,%3}, [%4];" \
        : "=r"(r0), "=r"(r1), "=r"(r2), "=r"(r3) : "r"(a))

__device__ __forceinline__ void mma16816(float* c, uint32_t a0, uint32_t a1,
    uint32_t a2, uint32_t a3, uint32_t b0, uint32_t b1, __nv_bfloat16) {
    asm volatile("mma.sync.aligned.m16n8k16.row.col.f32.bf16.bf16.f32 "
        "{%0,%1,%2,%3}, {%4,%5,%6,%7}, {%8,%9}, {%0,%1,%2,%3};"
        : "+f"(c[0]), "+f"(c[1]), "+f"(c[2]), "+f"(c[3])
        : "r"(a0), "r"(a1), "r"(a2), "r"(a3), "r"(b0), "r"(b1));
}
__device__ __forceinline__ void mma16816(float* c, uint32_t a0, uint32_t a1,
    uint32_t a2, uint32_t a3, uint32_t b0, uint32_t b1, __half) {
    asm volatile("mma.sync.aligned.m16n8k16.row.col.f32.f16.f16.f32 "
        "{%0,%1,%2,%3}, {%4,%5,%6,%7}, {%8,%9}, {%0,%1,%2,%3};"
        : "+f"(c[0]), "+f"(c[1]), "+f"(c[2]), "+f"(c[3])
        : "r"(a0), "r"(a1), "r"(a2), "r"(a3), "r"(b0), "r"(b1));
}

template<typename T>
__global__ __launch_bounds__(256) void mma_gemm_nt(
    const T* __restrict__ A, const T* __restrict__ B,
    float* __restrict__ C, int M, int N, int K, int ldc,
    float alpha, float beta, const float* __restrict__ bias)
{
    extern __shared__ __align__(128) char smem[];
    const uint32_t sbase = smem_u32(smem);
    const int tid = threadIdx.x;
    const int wid = tid >> 5;
    const int lane = tid & 31;
    const int wm = (wid & 1) * 64;
    const int wn = (wid >> 1) * 64;

    // grid swizzle: 8-row supergroups for L2 reuse (gridDim.y multiple of 8)
    const int nbx = gridDim.x;
    int id = blockIdx.y * nbx + blockIdx.x;
    int grp = id / (8 * nbx);
    int rem = id - grp * (8 * nbx);
    const int m0 = (grp * 8 + (rem & 7)) * BM;
    const int n0 = (rem >> 3) * BN;

    const T* gA = A + (size_t)m0 * K;
    const T* gB = B + (size_t)n0 * K;

    const int lrow = tid >> 3;           // 0..31
    const int lcol = (tid & 7) << 3;     // 0,8,...,56

    float acc[4][8][4];
    #pragma unroll
    for (int i = 0; i < 4; i++)
        #pragma unroll
        for (int j = 0; j < 8; j++)
            #pragma unroll
            for (int q = 0; q < 4; q++) acc[i][j][q] = 0.0f;

    const int KT = K / BK;

    #pragma unroll
    for (int s = 0; s < STAGES - 1; s++) {
        const int k0 = s * BK;
        uint32_t sa = sbase + s * STAGE_BYTES;
        uint32_t sb = sa + A_STAGE;
        #pragma unroll
        for (int h = 0; h < 4; h++) {
            int r = lrow + h * 32;
            CP_ASYNC16(sa + (uint32_t)(r * PAD + lcol) * 2, gA + (size_t)r * K + k0 + lcol);
        }
        #pragma unroll
        for (int h = 0; h < 8; h++) {
            int r = lrow + h * 32;
            CP_ASYNC16(sb + (uint32_t)(r * PAD + lcol) * 2, gB + (size_t)r * K + k0 + lcol);
        }
        CP_COMMIT();
    }

    const int a_row = wm + (lane & 15);
    const int a_half = (lane >> 4) << 3;
    const int b_row = wn + ((lane >> 4) << 3) + (lane & 7);
    const int b_half = ((lane >> 3) & 1) << 3;

    for (int kt = 0; kt < KT; kt++) {
        CP_WAIT1();
        __syncthreads();

        if (kt + STAGES - 1 < KT) {
            const int s = (kt + STAGES - 1) % STAGES;
            const int k0 = (kt + STAGES - 1) * BK;
            uint32_t sa = sbase + s * STAGE_BYTES;
            uint32_t sb = sa + A_STAGE;
            #pragma unroll
            for (int h = 0; h < 4; h++) {
                int r = lrow + h * 32;
                CP_ASYNC16(sa + (uint32_t)(r * PAD + lcol) * 2, gA + (size_t)r * K + k0 + lcol);
            }
            #pragma unroll
            for (int h = 0; h < 8; h++) {
                int r = lrow + h * 32;
                CP_ASYNC16(sb + (uint32_t)(r * PAD + lcol) * 2, gB + (size_t)r * K + k0 + lcol);
            }
        }
        CP_COMMIT();

        const int s = kt % STAGES;
        const uint32_t sa = sbase + s * STAGE_BYTES;
        const uint32_t sb = sa + A_STAGE;

        #pragma unroll
        for (int kk = 0; kk < 4; kk++) {
            uint32_t a0[4], a1[4], a2[4], a3[4];
            #pragma unroll
            for (int mt = 0; mt < 4; mt++) {
                uint32_t addr = sa + (uint32_t)((a_row + mt * 16) * PAD + kk * 16 + a_half) * 2;
                LDSM_X4(a0[mt], a1[mt], a2[mt], a3[mt], addr);
            }
            uint32_t b[8][2];
            #pragma unroll
            for (int g = 0; g < 4; g++) {
                uint32_t addr = sb + (uint32_t)((b_row + g * 16) * PAD + kk * 16 + b_half) * 2;
                uint32_t r0, r1, r2, r3;
                LDSM_X4(r0, r1, r2, r3, addr);
                b[g * 2 + 0][0] = r0; b[g * 2 + 0][1] = r1;
                b[g * 2 + 1][0] = r2; b[g * 2 + 1][1] = r3;
            }
            #pragma unroll
            for (int mt = 0; mt < 4; mt++)
                #pragma unroll
                for (int nt = 0; nt < 8; nt++)
                    mma16816(acc[mt][nt], a0[mt], a1[mt], a2[mt], a3[mt],
                             b[nt][0], b[nt][1], T{});
        }
        __syncthreads();
    }
    CP_WAIT0();

    const int er = lane >> 2;
    const int ec = (lane & 3) << 1;
    #pragma unroll
    for (int mt = 0; mt < 4; mt++) {
        #pragma unroll
        for (int nt = 0; nt < 8; nt++) {
            int col = n0 + wn + nt * 8 + ec;
            float b0 = bias ? bias[col] : 0.0f;
            float b1 = bias ? bias[col + 1] : 0.0f;
            #pragma unroll
            for (int half = 0; half < 2; half++) {
                int row = m0 + wm + mt * 16 + er + half * 8;
                float* Cp = C + (size_t)row * ldc + col;
                float v0 = alpha * acc[mt][nt][half * 2 + 0] + b0;
                float v1 = alpha * acc[mt][nt][half * 2 + 1] + b1;
                if (beta != 0.0f) { v0 += beta * Cp[0]; v1 += beta * Cp[1]; }
                *(float2*)Cp = make_float2(v0, v1);
            }
        }
    }
}

// ---------------- bf16 3-term split (contiguous) ----------------
__global__ void split_kernel(const float* __restrict__ src, __nv_bfloat16* __restrict__ dst,
                             int total, int logC, int lo_mid)
{
    int idx = blockIdx.x * blockDim.x + threadIdx.x;
    if (idx >= total) return;
    int C = 1 << logC;
    int r = idx >> logC;
    int c = idx & (C - 1);
    float x = src[idx];
    __nv_bfloat16 h = __float2bfloat16(x);
    __nv_bfloat16 l = __float2bfloat16(x - __bfloat162float(h));
    size_t base = (size_t)r * 3 * C + c;
    if (lo_mid) { dst[base] = h; dst[base + C] = l; dst[base + 2 * C] = h; }
    else        { dst[base] = h; dst[base + C] = h; dst[base + 2 * C] = l; }
}

// ---------------- bf16 3-term split from strided columns ----------------
// src rows have stride srcld; take C=256 cols starting at src_off
__global__ void split_strided(const float* __restrict__ src, int srcld, int src_off,
                              __nv_bfloat16* __restrict__ dst, int rows, int lo_mid)
{
    int idx = blockIdx.x * blockDim.x + threadIdx.x;
    if (idx >= rows * HH) return;
    int r = idx >> 8;
    int c = idx & 255;
    float x = src[(size_t)r * srcld + src_off + c];
    __nv_bfloat16 h = __float2bfloat16(x);
    __nv_bfloat16 l = __float2bfloat16(x - __bfloat162float(h));
    size_t base = (size_t)r * 3 * HH + c;
    if (lo_mid) { dst[base] = h; dst[base + HH] = l; dst[base + 2 * HH] = h; }
    else        { dst[base] = h; dst[base + HH] = h; dst[base + 2 * HH] = l; }
}

// ---------------- fp16 2-term A-layout split ----------------
__global__ void split2_f16(const float* __restrict__ src, __half* __restrict__ dst,
                           int total, int logC, float scale)
{
    int idx = blockIdx.x * blockDim.x + threadIdx.x;
    if (idx >= total) return;
    int C = 1 << logC;
    int r = idx >> logC;
    int c = idx & (C - 1);
    float x = src[idx] * scale;
    __half h = __float2half(x);
    __half l = __float2half(x - __half2float(h));
    size_t base = (size_t)r * 2 * C + c;
    dst[base] = h;
    dst[base + C] = l;
}

// ---------------- fp16 transpose + hi-dup B-layout ----------------
__global__ void split1t_f16(const float* __restrict__ src, __half* __restrict__ dst,
                            int R, int C, float scale)
{
    __shared__ float t[32][33];
    int c0 = blockIdx.x * 32, r0 = blockIdx.y * 32;
    int tx = threadIdx.x, ty = threadIdx.y;
    for (int i = ty; i < 32; i += 8)
        t[i][tx] = src[(size_t)(r0 + i) * C + c0 + tx];
    __syncthreads();
    for (int i = ty; i < 32; i += 8) {
        int c = c0 + i;
        int r = r0 + tx;
        __half h = __float2half(t[tx][i] * scale);
        size_t base = (size_t)c * 2 * R;
        dst[base + r] = h;
        dst[base + R + r] = h;
    }
}

// ---------------- aux kernels ----------------
__global__ void zero_kernel(float* out, int n) {
    int i = blockIdx.x * blockDim.x + threadIdx.x;
    if (i < n) out[i] = 0.0f;
}

__global__ void bias_build(const float* __restrict__ bq, const float* __restrict__ bk,
                           float* __restrict__ bias)
{
    int i = blockIdx.x * blockDim.x + threadIdx.x;
    if (i < 1024) bias[i] = bq[i];
    else if (i < 2048) bias[i] = bk[i - 1024];
}

__global__ void rownorm_kernel(const float* __restrict__ QK, int qoff, int koff,
                               float* __restrict__ qn, float* __restrict__ kn)
{
    int i = blockIdx.x;
    int tid = threadIdx.x;
    __shared__ float sq[256];
    __shared__ float sk[256];
    float q = QK[(size_t)i * NQK + qoff + tid];
    float k = QK[(size_t)i * NQK + koff + tid];
    sq[tid] = q * q;
    sk[tid] = k * k;
    __syncthreads();
    for (int s = 128; s > 0; s >>= 1) {
        if (tid < s) { sq[tid] += sq[tid + s]; sk[tid] += sk[tid + s]; }
        __syncthreads();
    }
    if (tid == 0) { qn[i] = sq[0]; kn[i] = sk[0]; }
}

__global__ void select_kernel(const float* __restrict__ G,
                              const float* __restrict__ qn, const float* __restrict__ kn,
                              float* __restrict__ md_out, float* __restrict__ kth_out)
{
    int i = blockIdx.x;
    int tid = threadIdx.x;
    __shared__ float sd[NN];
    __shared__ float rmin[256];
    __shared__ int ridx[256];
    __shared__ float sel[30];
    float qni = qn[i];
    const float* Gi = G + (size_t)i * NN;
    for (int j = tid; j < NN; j += 256) {
        float sq = qni + kn[j] - 2.0f * Gi[j];
        sd[j] = sqrtf(fmaxf(sq, 0.0f) + 1e-10f);
    }
    __syncthreads();
    for (int it = 0; it < 30; it++) {
        float mv = FLT_MAX;
        int mi = -1;
        for (int j = tid; j < NN; j += 256) {
            float v = sd[j];
            if (v < mv) { mv = v; mi = j; }
        }
        rmin[tid] = mv;
        ridx[tid] = mi;
        __syncthreads();
        for (int s = 128; s > 0; s >>= 1) {
            if (tid < s) {
                float v2 = rmin[tid + s];
                if (v2 < rmin[tid] || (v2 == rmin[tid] && ridx[tid + s] < ridx[tid])) {
                    rmin[tid] = v2;
                    ridx[tid] = ridx[tid + s];
                }
            }
            __syncthreads();
        }
        if (tid == 0) {
            sel[it] = rmin[0];
            sd[ridx[0]] = FLT_MAX;
        }
        __syncthreads();
    }
    if (tid == 0) {
        float mdp = sel[10] + 1e-10f;
        float t = sel[29] / mdp;
        md_out[i] = mdp;
        kth_out[i] = expf(-(t * t));
    }
}

__global__ void aff_kernel(float* __restrict__ A,
                           const float* __restrict__ qn, const float* __restrict__ kn,
                           const float* __restrict__ mdp, const float* __restrict__ kth)
{
    size_t idx = (size_t)blockIdx.x * blockDim.x + threadIdx.x;
    if (idx >= (size_t)NN * NN) return;
    int i = (int)(idx >> 12);
    int j = (int)(idx & 4095);
    float sq = qn[i] + kn[j] - 2.0f * A[idx];
    float d = sqrtf(fmaxf(sq, 0.0f) + 1e-10f);
    float dd = d / mdp[i];
    float a = expf(-(dd * dd));
    float r = (a >= kth[i]) ? a : 0.0f;
    if (j == i) r = 1.0f;
    A[idx] = r;
}

__global__ void transadd_kernel(const float* __restrict__ A, float* __restrict__ B)
{
    __shared__ float tile[32][33];
    int x0 = blockIdx.x * 32;
    int y0 = blockIdx.y * 32;
    int tx = threadIdx.x;
    int ty = threadIdx.y;
    for (int r = ty; r < 32; r += 8)
        tile[r][tx] = A[(size_t)(x0 + r) * NN + y0 + tx];
    __syncthreads();
    for (int r = ty; r < 32; r += 8) {
        size_t idx = (size_t)(y0 + r) * NN + x0 + tx;
        B[idx] = A[idx] + tile[tx][r];
    }
}

__global__ void softmax_kernel(float* __restrict__ P)
{
    int i = blockIdx.x;
    int tid = threadIdx.x;
    __shared__ float s[NN];
    __shared__ float red[256];
    size_t base = (size_t)i * NN;
    float m = -FLT_MAX;
    for (int j = tid; j < NN; j += 256) {
        float v = P[base + j];
        s[j] = v;
        m = fmaxf(m, v);
    }
    red[tid] = m;
    __syncthreads();
    for (int st = 128; st > 0; st >>= 1) {
        if (tid < st) red[tid] = fmaxf(red[tid], red[tid + st]);
        __syncthreads();
    }
    m = red[0];
    __syncthreads();
    float sum = 0.0f;
    for (int j = tid; j < NN; j += 256) {
        float e = expf(s[j] - m);
        s[j] = e;
        sum += e;
    }
    red[tid] = sum;
    __syncthreads();
    for (int st = 128; st > 0; st >>= 1) {
        if (tid < st) red[tid] += red[tid + st];
        __syncthreads();
    }
    float inv = 1.0f / red[0];
    for (int j = tid; j < NN; j += 256)
        P[base + j] = s[j] * inv;
}

// ---------------- launch ----------------
template<typename T>
static void run_gemm(const T* A, const T* B, float* C, int M, int N, int K, int ldc,
                     float alpha, float beta, const float* bias)
{
    dim3 grid(N / BN, M / BM);
    mma_gemm_nt<T><<<grid, 256, GEMM_SMEM>>>(A, B, C, M, N, K, ldc, alpha, beta, bias);
}

extern "C" void kernel_launch(void* const* d_in, const int* in_sizes, int n_in,
                              void* d_out, int out_size)
{
    const float* X  = (const float*)d_in[0];
    const float* Wq = (const float*)d_in[1];
    const float* bq = (const float*)d_in[2];
    const float* Wk = (const float*)d_in[3];
    const float* bk = (const float*)d_in[4];
    float* out = (float*)d_out;

    static int smem_set = 0;
    if (!smem_set) {
        cudaFuncSetAttribute(mma_gemm_nt<__nv_bfloat16>,
                             cudaFuncAttributeMaxDynamicSharedMemorySize, GEMM_SMEM);
        cudaFuncSetAttribute(mma_gemm_nt<__half>,
                             cudaFuncAttributeMaxDynamicSharedMemorySize, GEMM_SMEM);
        smem_set = 1;
    }

    float *QK, *bias, *qn, *kn, *md, *kth, *A, *P, *Y, *Y2;
    __nv_bfloat16 *Xa, *Wall, *Qa, *Kb;
    __half *Pa, *XtB, *YtB;
    cudaGetSymbolAddress((void**)&QK,   g_QK);
    cudaGetSymbolAddress((void**)&bias, g_bias);
    cudaGetSymbolAddress((void**)&qn,  g_qn);
    cudaGetSymbolAddress((void**)&kn,  g_kn);
    cudaGetSymbolAddress((void**)&md,  g_md);
    cudaGetSymbolAddress((void**)&kth, g_kth);
    cudaGetSymbolAddress((void**)&A,   g_A);
    cudaGetSymbolAddress((void**)&P,   g_P);
    cudaGetSymbolAddress((void**)&Y,   g_Y);
    cudaGetSymbolAddress((void**)&Y2,  g_Y2);
    cudaGetSymbolAddress((void**)&Xa,   s_Xa);
    cudaGetSymbolAddress((void**)&Wall, s_Wall);
    cudaGetSymbolAddress((void**)&Qa,   s_Qa);
    cudaGetSymbolAddress((void**)&Kb,   s_Kb);
    cudaGetSymbolAddress((void**)&Pa,  f_Pa);
    cudaGetSymbolAddress((void**)&XtB, f_XtB);
    cudaGetSymbolAddress((void**)&YtB, f_YtB);

    const float invP  = 1.0f / SCALE_P;
    const float invPY = 1.0f / (SCALE_P * SCALE_Y);

    // ---- setup (once) ----
    split_kernel<<<(NN * DD + 255) / 256, 256>>>(X, Xa, NN * DD, 11, 1);
    split1t_f16<<<dim3(DD / 32, NN / 32), dim3(32, 8)>>>(X, XtB, NN, DD, 1.0f);
    split_kernel<<<(1024 * DD + 255) / 256, 256>>>(Wq, Wall, 1024 * DD, 11, 0);
    split_kernel<<<(1024 * DD + 255) / 256, 256>>>(Wk, Wall + (size_t)1024 * K3DD, 1024 * DD, 11, 0);
    bias_build<<<(NQK + 255) / 256, 256>>>(bq, bk, bias);

    // combined projections: QK = X @ [Wq||Wk]^T + bias  (one full-chip GEMM)
    run_gemm(Xa, Wall, QK, NN, NQK, K3DD, NQK, 1.0f, 0.0f, bias);

    zero_kernel<<<(NN * DD + 255) / 256, 256>>>(out, NN * DD);

    for (int h = 0; h < HEADS; h++) {
        const int qoff = h * HH;
        const int koff = 1024 + h * HH;

        rownorm_kernel<<<NN, 256>>>(QK, qoff, koff, qn, kn);

        // gram = Q_h @ K_h^T (bf16 3-term)
        split_strided<<<(NN * HH + 255) / 256, 256>>>(QK, NQK, qoff, Qa, NN, 1);
        split_strided<<<(NN * HH + 255) / 256, 256>>>(QK, NQK, koff, Kb, NN, 0);
        run_gemm(Qa, Kb, A, NN, NN, K3HH, NN, 1.0f, 0.0f, nullptr);

        select_kernel<<<NN, 256>>>(A, qn, kn, md, kth);
        aff_kernel<<<(int)(((size_t)NN * NN + 255) / 256), 256>>>(A, qn, kn, md, kth);
        transadd_kernel<<<dim3(NN / 32, NN / 32), dim3(32, 8)>>>(A, P);
        softmax_kernel<<<NN, 256>>>(P);

        // split P once (fp16 2-term, scaled); apply P six times
        split2_f16<<<(int)(((size_t)NN * NN + 255) / 256), 256>>>(P, Pa, NN * NN, 12, SCALE_P);

        run_gemm(Pa, XtB, Y, NN, DD, K2NN, DD, invP, 0.0f, nullptr);
        split1t_f16<<<dim3(DD / 32, NN / 32), dim3(32, 8)>>>(Y, YtB, NN, DD, SCALE_Y);
        run_gemm(Pa, YtB, Y2, NN, DD, K2NN, DD, invPY, 0.0f, nullptr);
        split1t_f16<<<dim3(DD / 32, NN / 32), dim3(32, 8)>>>(Y2, YtB, NN, DD, SCALE_Y);
        run_gemm(Pa, YtB, Y, NN, DD, K2NN, DD, invPY, 0.0f, nullptr);
        split1t_f16<<<dim3(DD / 32, NN / 32), dim3(32, 8)>>>(Y, YtB, NN, DD, SCALE_Y);
        run_gemm(Pa, YtB, Y2, NN, DD, K2NN, DD, invPY, 0.0f, nullptr);
        split1t_f16<<<dim3(DD / 32, NN / 32), dim3(32, 8)>>>(Y2, YtB, NN, DD, SCALE_Y);
        run_gemm(Pa, YtB, Y, NN, DD, K2NN, DD, invPY, 0.0f, nullptr);
        split1t_f16<<<dim3(DD / 32, NN / 32), dim3(32, 8)>>>(Y, YtB, NN, DD, SCALE_Y);
        run_gemm(Pa, YtB, out, NN, DD, K2NN, DD, 0.25f * invPY, 1.0f, nullptr);
    }
}

// round 6
// speedup vs baseline: 5.9774x; 1.8618x over previous
#include <cuda_runtime.h>
#include <cuda_bf16.h>
#include <math.h>
#include <float.h>
#include <stdint.h>

#define NN 4096
#define DD 2048
#define HH 256
#define HEADS 4
#define K3DD (3*DD)
#define K3HH (3*HH)
#define NQK 2048
#define SPW 2048          // max nnz storage per row

// ---------------- static device scratch ----------------
__device__ float g_QK[(size_t)NN * NQK];
__device__ float g_bias[NQK];
__device__ float g_qn[NN];
__device__ float g_kn[NN];
__device__ float g_md[NN];
__device__ float g_kth[NN];
__device__ float g_A[(size_t)NN * NN];     // gram -> pruned aff
__device__ float g_M[(size_t)NN * NN];     // A + A^T
__device__ float g_Y[(size_t)NN * DD];
__device__ float g_Y2[(size_t)NN * DD];

__device__ int   g_cols[(size_t)NN * SPW];
__device__ float g_wv[(size_t)NN * SPW];
__device__ int   g_cnt[NN];
__device__ float g_Z[NN];
__device__ float g_cX[DD];                 // colsum of X (shared across heads)
__device__ float g_c[DD];                  // colsum of current Y
__device__ float g_cpart[32 * DD];

__device__ __nv_bfloat16 s_Xa[(size_t)NN * K3DD];
__device__ __nv_bfloat16 s_Wall[(size_t)NQK * K3DD];
__device__ __nv_bfloat16 s_Qa[(size_t)NN * K3HH];
__device__ __nv_bfloat16 s_Kb[(size_t)NN * K3HH];

// ---------------- mma.sync NT GEMM: 128x256 CTA, 64x64 warp, BK=64 ----------------
#define BM 128
#define BN 256
#define BK 64
#define STAGES 3
#define PAD 72
#define A_STAGE (BM * PAD * 2)
#define B_STAGE (BN * PAD * 2)
#define STAGE_BYTES (A_STAGE + B_STAGE)
#define GEMM_SMEM (STAGES * STAGE_BYTES)

__device__ __forceinline__ uint32_t smem_u32(const void* p) {
    uint32_t a;
    asm("{ .reg .u64 t; cvta.to.shared.u64 t, %1; cvt.u32.u64 %0, t; }" : "=r"(a) : "l"(p));
    return a;
}
#define CP_ASYNC16(sa, ga) \
    asm volatile("cp.async.cg.shared.global [%0], [%1], 16;" :: "r"(sa), "l"(ga))
#define CP_COMMIT() asm volatile("cp.async.commit_group;" ::: "memory")
#define CP_WAIT1()  asm volatile("cp.async.wait_group 1;" ::: "memory")
#define CP_WAIT0()  asm volatile("cp.async.wait_group 0;" ::: "memory")
#define LDSM_X4(r0, r1, r2, r3, a) \
    asm volatile("ldmatrix.sync.aligned.m8n8.x4.shared.b16 {%0,%1,%2,%3}, [%4];" \
        : "=r"(r0), "=r"(r1), "=r"(r2), "=r"(r3) : "r"(a))
#define MMA16816(c, a0, a1, a2, a3, b0, b1) \
    asm volatile("mma.sync.aligned.m16n8k16.row.col.f32.bf16.bf16.f32 " \
        "{%0,%1,%2,%3}, {%4,%5,%6,%7}, {%8,%9}, {%0,%1,%2,%3};" \
        : "+f"((c)[0]), "+f"((c)[1]), "+f"((c)[2]), "+f"((c)[3]) \
        : "r"(a0), "r"(a1), "r"(a2), "r"(a3), "r"(b0), "r"(b1))

__global__ __launch_bounds__(256) void mma_gemm_nt(
    const __nv_bfloat16* __restrict__ A, const __nv_bfloat16* __restrict__ B,
    float* __restrict__ C, int M, int N, int K, int ldc,
    const float* __restrict__ bias)
{
    extern __shared__ __align__(128) char smem[];
    const uint32_t sbase = smem_u32(smem);
    const int tid = threadIdx.x;
    const int wid = tid >> 5;
    const int lane = tid & 31;
    const int wm = (wid & 1) * 64;
    const int wn = (wid >> 1) * 64;

    const int nbx = gridDim.x;
    int id = blockIdx.y * nbx + blockIdx.x;
    int grp = id / (8 * nbx);
    int rem = id - grp * (8 * nbx);
    const int m0 = (grp * 8 + (rem & 7)) * BM;
    const int n0 = (rem >> 3) * BN;

    const __nv_bfloat16* gA = A + (size_t)m0 * K;
    const __nv_bfloat16* gB = B + (size_t)n0 * K;

    const int lrow = tid >> 3;
    const int lcol = (tid & 7) << 3;

    float acc[4][8][4];
    #pragma unroll
    for (int i = 0; i < 4; i++)
        #pragma unroll
        for (int j = 0; j < 8; j++)
            #pragma unroll
            for (int q = 0; q < 4; q++) acc[i][j][q] = 0.0f;

    const int KT = K / BK;

    #pragma unroll
    for (int s = 0; s < STAGES - 1; s++) {
        const int k0 = s * BK;
        uint32_t sa = sbase + s * STAGE_BYTES;
        uint32_t sb = sa + A_STAGE;
        #pragma unroll
        for (int h = 0; h < 4; h++) {
            int r = lrow + h * 32;
            CP_ASYNC16(sa + (uint32_t)(r * PAD + lcol) * 2, gA + (size_t)r * K + k0 + lcol);
        }
        #pragma unroll
        for (int h = 0; h < 8; h++) {
            int r = lrow + h * 32;
            CP_ASYNC16(sb + (uint32_t)(r * PAD + lcol) * 2, gB + (size_t)r * K + k0 + lcol);
        }
        CP_COMMIT();
    }

    const int a_row = wm + (lane & 15);
    const int a_half = (lane >> 4) << 3;
    const int b_row = wn + ((lane >> 4) << 3) + (lane & 7);
    const int b_half = ((lane >> 3) & 1) << 3;

    for (int kt = 0; kt < KT; kt++) {
        CP_WAIT1();
        __syncthreads();

        if (kt + STAGES - 1 < KT) {
            const int s = (kt + STAGES - 1) % STAGES;
            const int k0 = (kt + STAGES - 1) * BK;
            uint32_t sa = sbase + s * STAGE_BYTES;
            uint32_t sb = sa + A_STAGE;
            #pragma unroll
            for (int h = 0; h < 4; h++) {
                int r = lrow + h * 32;
                CP_ASYNC16(sa + (uint32_t)(r * PAD + lcol) * 2, gA + (size_t)r * K + k0 + lcol);
            }
            #pragma unroll
            for (int h = 0; h < 8; h++) {
                int r = lrow + h * 32;
                CP_ASYNC16(sb + (uint32_t)(r * PAD + lcol) * 2, gB + (size_t)r * K + k0 + lcol);
            }
        }
        CP_COMMIT();

        const int s = kt % STAGES;
        const uint32_t sa = sbase + s * STAGE_BYTES;
        const uint32_t sb = sa + A_STAGE;

        #pragma unroll
        for (int kk = 0; kk < 4; kk++) {
            uint32_t a0[4], a1[4], a2[4], a3[4];
            #pragma unroll
            for (int mt = 0; mt < 4; mt++) {
                uint32_t addr = sa + (uint32_t)((a_row + mt * 16) * PAD + kk * 16 + a_half) * 2;
                LDSM_X4(a0[mt], a1[mt], a2[mt], a3[mt], addr);
            }
            uint32_t b[8][2];
            #pragma unroll
            for (int g = 0; g < 4; g++) {
                uint32_t addr = sb + (uint32_t)((b_row + g * 16) * PAD + kk * 16 + b_half) * 2;
                uint32_t r0, r1, r2, r3;
                LDSM_X4(r0, r1, r2, r3, addr);
                b[g * 2 + 0][0] = r0; b[g * 2 + 0][1] = r1;
                b[g * 2 + 1][0] = r2; b[g * 2 + 1][1] = r3;
            }
            #pragma unroll
            for (int mt = 0; mt < 4; mt++)
                #pragma unroll
                for (int nt = 0; nt < 8; nt++)
                    MMA16816(acc[mt][nt], a0[mt], a1[mt], a2[mt], a3[mt],
                             b[nt][0], b[nt][1]);
        }
        __syncthreads();
    }
    CP_WAIT0();

    const int er = lane >> 2;
    const int ec = (lane & 3) << 1;
    #pragma unroll
    for (int mt = 0; mt < 4; mt++) {
        #pragma unroll
        for (int nt = 0; nt < 8; nt++) {
            int col = n0 + wn + nt * 8 + ec;
            float b0 = bias ? bias[col] : 0.0f;
            float b1 = bias ? bias[col + 1] : 0.0f;
            #pragma unroll
            for (int half = 0; half < 2; half++) {
                int row = m0 + wm + mt * 16 + er + half * 8;
                float* Cp = C + (size_t)row * ldc + col;
                *(float2*)Cp = make_float2(acc[mt][nt][half * 2 + 0] + b0,
                                           acc[mt][nt][half * 2 + 1] + b1);
            }
        }
    }
}

// ---------------- splits ----------------
__global__ void split_kernel(const float* __restrict__ src, __nv_bfloat16* __restrict__ dst,
                             int total, int logC, int lo_mid)
{
    int idx = blockIdx.x * blockDim.x + threadIdx.x;
    if (idx >= total) return;
    int C = 1 << logC;
    int r = idx >> logC;
    int c = idx & (C - 1);
    float x = src[idx];
    __nv_bfloat16 h = __float2bfloat16(x);
    __nv_bfloat16 l = __float2bfloat16(x - __bfloat162float(h));
    size_t base = (size_t)r * 3 * C + c;
    if (lo_mid) { dst[base] = h; dst[base + C] = l; dst[base + 2 * C] = h; }
    else        { dst[base] = h; dst[base + C] = h; dst[base + 2 * C] = l; }
}

__global__ void split_strided(const float* __restrict__ src, int srcld, int src_off,
                              __nv_bfloat16* __restrict__ dst, int rows, int lo_mid)
{
    int idx = blockIdx.x * blockDim.x + threadIdx.x;
    if (idx >= rows * HH) return;
    int r = idx >> 8;
    int c = idx & 255;
    float x = src[(size_t)r * srcld + src_off + c];
    __nv_bfloat16 h = __float2bfloat16(x);
    __nv_bfloat16 l = __float2bfloat16(x - __bfloat162float(h));
    size_t base = (size_t)r * 3 * HH + c;
    if (lo_mid) { dst[base] = h; dst[base + HH] = l; dst[base + 2 * HH] = h; }
    else        { dst[base] = h; dst[base + HH] = h; dst[base + 2 * HH] = l; }
}

// ---------------- aux kernels (selection path) ----------------
__global__ void zero_kernel(float* out, int n) {
    int i = blockIdx.x * blockDim.x + threadIdx.x;
    if (i < n) out[i] = 0.0f;
}

__global__ void bias_build(const float* __restrict__ bq, const float* __restrict__ bk,
                           float* __restrict__ bias)
{
    int i = blockIdx.x * blockDim.x + threadIdx.x;
    if (i < 1024) bias[i] = bq[i];
    else if (i < 2048) bias[i] = bk[i - 1024];
}

__global__ void rownorm_kernel(const float* __restrict__ QK, int qoff, int koff,
                               float* __restrict__ qn, float* __restrict__ kn)
{
    int i = blockIdx.x;
    int tid = threadIdx.x;
    __shared__ float sq[256];
    __shared__ float sk[256];
    float q = QK[(size_t)i * NQK + qoff + tid];
    float k = QK[(size_t)i * NQK + koff + tid];
    sq[tid] = q * q;
    sk[tid] = k * k;
    __syncthreads();
    for (int s = 128; s > 0; s >>= 1) {
        if (tid < s) { sq[tid] += sq[tid + s]; sk[tid] += sk[tid + s]; }
        __syncthreads();
    }
    if (tid == 0) { qn[i] = sq[0]; kn[i] = sk[0]; }
}

__global__ void select_kernel(const float* __restrict__ G,
                              const float* __restrict__ qn, const float* __restrict__ kn,
                              float* __restrict__ md_out, float* __restrict__ kth_out)
{
    int i = blockIdx.x;
    int tid = threadIdx.x;
    __shared__ float sd[NN];
    __shared__ float rmin[256];
    __shared__ int ridx[256];
    __shared__ float sel[30];
    float qni = qn[i];
    const float* Gi = G + (size_t)i * NN;
    for (int j = tid; j < NN; j += 256) {
        float sq = qni + kn[j] - 2.0f * Gi[j];
        sd[j] = sqrtf(fmaxf(sq, 0.0f) + 1e-10f);
    }
    __syncthreads();
    for (int it = 0; it < 30; it++) {
        float mv = FLT_MAX;
        int mi = -1;
        for (int j = tid; j < NN; j += 256) {
            float v = sd[j];
            if (v < mv) { mv = v; mi = j; }
        }
        rmin[tid] = mv;
        ridx[tid] = mi;
        __syncthreads();
        for (int s = 128; s > 0; s >>= 1) {
            if (tid < s) {
                float v2 = rmin[tid + s];
                if (v2 < rmin[tid] || (v2 == rmin[tid] && ridx[tid + s] < ridx[tid])) {
                    rmin[tid] = v2;
                    ridx[tid] = ridx[tid + s];
                }
            }
            __syncthreads();
        }
        if (tid == 0) {
            sel[it] = rmin[0];
            sd[ridx[0]] = FLT_MAX;
        }
        __syncthreads();
    }
    if (tid == 0) {
        float mdp = sel[10] + 1e-10f;
        float t = sel[29] / mdp;
        md_out[i] = mdp;
        kth_out[i] = expf(-(t * t));
    }
}

__global__ void aff_kernel(float* __restrict__ A,
                           const float* __restrict__ qn, const float* __restrict__ kn,
                           const float* __restrict__ mdp, const float* __restrict__ kth)
{
    size_t idx = (size_t)blockIdx.x * blockDim.x + threadIdx.x;
    if (idx >= (size_t)NN * NN) return;
    int i = (int)(idx >> 12);
    int j = (int)(idx & 4095);
    float sq = qn[i] + kn[j] - 2.0f * A[idx];
    float d = sqrtf(fmaxf(sq, 0.0f) + 1e-10f);
    float dd = d / mdp[i];
    float a = expf(-(dd * dd));
    float r = (a >= kth[i]) ? a : 0.0f;
    if (j == i) r = 1.0f;
    A[idx] = r;
}

__global__ void transadd_kernel(const float* __restrict__ A, float* __restrict__ B)
{
    __shared__ float tile[32][33];
    int x0 = blockIdx.x * 32;
    int y0 = blockIdx.y * 32;
    int tx = threadIdx.x;
    int ty = threadIdx.y;
    for (int r = ty; r < 32; r += 8)
        tile[r][tx] = A[(size_t)(x0 + r) * NN + y0 + tx];
    __syncthreads();
    for (int r = ty; r < 32; r += 8) {
        size_t idx = (size_t)(y0 + r) * NN + x0 + tx;
        B[idx] = A[idx] + tile[tx][r];
    }
}

// ---------------- sparse structure build (deterministic, j-ascending) ----------------
__global__ void build_sparse(const float* __restrict__ M, int* __restrict__ cols,
                             float* __restrict__ wv, int* __restrict__ cnt,
                             float* __restrict__ Z)
{
    int i = blockIdx.x;
    int t = threadIdx.x;
    __shared__ int sc[256];
    __shared__ float zr[256];
    const float* Mi = M + (size_t)i * NN;
    // pass 1: count + Z partial over segment [t*16, t*16+16)
    int c = 0;
    float zs = 0.0f;
    #pragma unroll
    for (int k = 0; k < 16; k++) {
        float v = Mi[t * 16 + k];
        if (v != 0.0f) { c++; zs += __expf(0.0f) * expf(v); }
    }
    sc[t] = c;
    zr[t] = zs;
    __syncthreads();
    // inclusive scan over counts (deterministic)
    for (int d = 1; d < 256; d <<= 1) {
        int x = (t >= d) ? sc[t - d] : 0;
        __syncthreads();
        sc[t] += x;
        __syncthreads();
    }
    int off = sc[t] - c;   // exclusive
    int total = sc[255];
    // pass 2: write entries in order
    int p = 0;
    int* ci = cols + (size_t)i * SPW;
    float* wi = wv + (size_t)i * SPW;
    #pragma unroll
    for (int k = 0; k < 16; k++) {
        float v = Mi[t * 16 + k];
        if (v != 0.0f) {
            int o = off + p;
            if (o < SPW) { ci[o] = t * 16 + k; wi[o] = expf(v) - 1.0f; }
            p++;
        }
    }
    __syncthreads();
    // Z tree reduce
    for (int s = 128; s > 0; s >>= 1) {
        if (t < s) zr[t] += zr[t + s];
        __syncthreads();
    }
    if (t == 0) {
        int tt = total > SPW ? SPW : total;
        cnt[i] = tt;
        Z[i] = (float)(NN - total) + zr[0];
    }
}

// ---------------- colsum: partials over 128-row slabs, then reduce ----------------
__global__ void colsum_part(const float* __restrict__ Y, float* __restrict__ part)
{
    int col = blockIdx.x * 256 + threadIdx.x;   // gridDim.x = 8
    int slab = blockIdx.y;                      // 32 slabs of 128 rows
    float s = 0.0f;
    const float* p = Y + (size_t)slab * 128 * DD + col;
    #pragma unroll 4
    for (int r = 0; r < 128; r++) s += p[(size_t)r * DD];
    part[slab * DD + col] = s;
}
__global__ void colsum_fin(const float* __restrict__ part, float* __restrict__ c)
{
    int col = blockIdx.x * 256 + threadIdx.x;
    float s = 0.0f;
    #pragma unroll
    for (int k = 0; k < 32; k++) s += part[k * DD + col];
    c[col] = s;
}

// ---------------- sparse apply: Yout[i,:] = alpha*(c + sum w_ij Y[j,:])/Z_i (+accum) ----------------
__global__ __launch_bounds__(256) void spmm_kernel(
    const int* __restrict__ cols, const float* __restrict__ wv,
    const int* __restrict__ cnt, const float* __restrict__ Z,
    const float* __restrict__ c, const float* __restrict__ Yin,
    float* __restrict__ Yout, float alpha, int accum)
{
    const int i = blockIdx.y;
    const int d = blockIdx.x * 512 + threadIdx.x;   // gridDim.x = 4
    float a0 = c[d];
    float a1 = c[d + 256];
    const int n = cnt[i];
    const int* ci = cols + (size_t)i * SPW;
    const float* wi = wv + (size_t)i * SPW;
    #pragma unroll 4
    for (int k = 0; k < n; k++) {
        int j = ci[k];
        float w = wi[k];
        const float* Yj = Yin + (size_t)j * DD + d;
        a0 = fmaf(w, Yj[0], a0);
        a1 = fmaf(w, Yj[256], a1);
    }
    float s = alpha / Z[i];
    float* o = Yout + (size_t)i * DD + d;
    if (accum) {
        o[0] += s * a0;
        o[256] += s * a1;
    } else {
        o[0] = s * a0;
        o[256] = s * a1;
    }
}

// ---------------- launch ----------------
static void run_gemm(const __nv_bfloat16* A, const __nv_bfloat16* B, float* C,
                     int M, int N, int K, int ldc, const float* bias)
{
    dim3 grid(N / BN, M / BM);
    mma_gemm_nt<<<grid, 256, GEMM_SMEM>>>(A, B, C, M, N, K, ldc, bias);
}

extern "C" void kernel_launch(void* const* d_in, const int* in_sizes, int n_in,
                              void* d_out, int out_size)
{
    const float* X  = (const float*)d_in[0];
    const float* Wq = (const float*)d_in[1];
    const float* bq = (const float*)d_in[2];
    const float* Wk = (const float*)d_in[3];
    const float* bk = (const float*)d_in[4];
    float* out = (float*)d_out;

    static int smem_set = 0;
    if (!smem_set) {
        cudaFuncSetAttribute(mma_gemm_nt, cudaFuncAttributeMaxDynamicSharedMemorySize,
                             GEMM_SMEM);
        smem_set = 1;
    }

    float *QK, *bias, *qn, *kn, *md, *kth, *A, *M, *Y, *Y2;
    float *wv, *Z, *cX, *c, *cpart;
    int *cols, *cnt;
    __nv_bfloat16 *Xa, *Wall, *Qa, *Kb;
    cudaGetSymbolAddress((void**)&QK,   g_QK);
    cudaGetSymbolAddress((void**)&bias, g_bias);
    cudaGetSymbolAddress((void**)&qn,  g_qn);
    cudaGetSymbolAddress((void**)&kn,  g_kn);
    cudaGetSymbolAddress((void**)&md,  g_md);
    cudaGetSymbolAddress((void**)&kth, g_kth);
    cudaGetSymbolAddress((void**)&A,   g_A);
    cudaGetSymbolAddress((void**)&M,   g_M);
    cudaGetSymbolAddress((void**)&Y,   g_Y);
    cudaGetSymbolAddress((void**)&Y2,  g_Y2);
    cudaGetSymbolAddress((void**)&cols, g_cols);
    cudaGetSymbolAddress((void**)&wv,   g_wv);
    cudaGetSymbolAddress((void**)&cnt,  g_cnt);
    cudaGetSymbolAddress((void**)&Z,    g_Z);
    cudaGetSymbolAddress((void**)&cX,   g_cX);
    cudaGetSymbolAddress((void**)&c,    g_c);
    cudaGetSymbolAddress((void**)&cpart, g_cpart);
    cudaGetSymbolAddress((void**)&Xa,   s_Xa);
    cudaGetSymbolAddress((void**)&Wall, s_Wall);
    cudaGetSymbolAddress((void**)&Qa,   s_Qa);
    cudaGetSymbolAddress((void**)&Kb,   s_Kb);

    // ---- setup ----
    split_kernel<<<(NN * DD + 255) / 256, 256>>>(X, Xa, NN * DD, 11, 1);
    split_kernel<<<(1024 * DD + 255) / 256, 256>>>(Wq, Wall, 1024 * DD, 11, 0);
    split_kernel<<<(1024 * DD + 255) / 256, 256>>>(Wk, Wall + (size_t)1024 * K3DD, 1024 * DD, 11, 0);
    bias_build<<<(NQK + 255) / 256, 256>>>(bq, bk, bias);
    colsum_part<<<dim3(8, 32), 256>>>(X, cpart);
    colsum_fin<<<8, 256>>>(cpart, cX);
    zero_kernel<<<(NN * DD + 255) / 256, 256>>>(out, NN * DD);

    // combined projections
    run_gemm(Xa, Wall, QK, NN, NQK, K3DD, NQK, bias);

    for (int h = 0; h < HEADS; h++) {
        const int qoff = h * HH;
        const int koff = 1024 + h * HH;

        rownorm_kernel<<<NN, 256>>>(QK, qoff, koff, qn, kn);
        split_strided<<<(NN * HH + 255) / 256, 256>>>(QK, NQK, qoff, Qa, NN, 1);
        split_strided<<<(NN * HH + 255) / 256, 256>>>(QK, NQK, koff, Kb, NN, 0);
        run_gemm(Qa, Kb, A, NN, NN, K3HH, NN, nullptr);

        select_kernel<<<NN, 256>>>(A, qn, kn, md, kth);
        aff_kernel<<<(int)(((size_t)NN * NN + 255) / 256), 256>>>(A, qn, kn, md, kth);
        transadd_kernel<<<dim3(NN / 32, NN / 32), dim3(32, 8)>>>(A, M);
        build_sparse<<<NN, 256>>>(M, cols, wv, cnt, Z);

        // six sparse applies: X -> Y -> Y2 -> Y -> Y2 -> Y -> out(+)
        dim3 sg(4, NN);
        spmm_kernel<<<sg, 256>>>(cols, wv, cnt, Z, cX, X, Y, 1.0f, 0);
        colsum_part<<<dim3(8, 32), 256>>>(Y, cpart);
        colsum_fin<<<8, 256>>>(cpart, c);
        spmm_kernel<<<sg, 256>>>(cols, wv, cnt, Z, c, Y, Y2, 1.0f, 0);
        colsum_part<<<dim3(8, 32), 256>>>(Y2, cpart);
        colsum_fin<<<8, 256>>>(cpart, c);
        spmm_kernel<<<sg, 256>>>(cols, wv, cnt, Z, c, Y2, Y, 1.0f, 0);
        colsum_part<<<dim3(8, 32), 256>>>(Y, cpart);
        colsum_fin<<<8, 256>>>(cpart, c);
        spmm_kernel<<<sg, 256>>>(cols, wv, cnt, Z, c, Y, Y2, 1.0f, 0);
        colsum_part<<<dim3(8, 32), 256>>>(Y2, cpart);
        colsum_fin<<<8, 256>>>(cpart, c);
        spmm_kernel<<<sg, 256>>>(cols, wv, cnt, Z, c, Y2, Y, 1.0f, 0);
        colsum_part<<<dim3(8, 32), 256>>>(Y, cpart);
        colsum_fin<<<8, 256>>>(cpart, c);
        spmm_kernel<<<sg, 256>>>(cols, wv, cnt, Z, c, Y, out, 0.25f, 1);
    }
}

// round 7
// speedup vs baseline: 6.7249x; 1.1251x over previous
#include <cuda_runtime.h>
#include <cuda_bf16.h>
#include <cuda_fp16.h>
#include <math.h>
#include <float.h>
#include <stdint.h>

#define NN 4096
#define DD 2048
#define HH 256
#define HEADS 4
#define K3DD (3*2048)
#define K3HH (3*256)
#define NQK 2048
#define SPW 2048

// ---------------- static device scratch ----------------
__device__ float g_QK[(size_t)NN * NQK];
__device__ float g_bias[NQK];
__device__ float g_qn[NN];
__device__ float g_kn[NN];
__device__ float g_md[NN];
__device__ float g_kth[NN];
__device__ float g_A[(size_t)NN * NN];     // gram
__device__ float g_M[(size_t)NN * NN];     // fused aff + aff^T
__device__ __half h_X[(size_t)NN * DD];    // fp16 X
__device__ __half h_Y[(size_t)NN * DD];
__device__ __half h_Y2[(size_t)NN * DD];

__device__ int   g_cols[(size_t)NN * SPW];
__device__ float g_wv[(size_t)NN * SPW];
__device__ int   g_cnt[NN];
__device__ float g_Z[NN];
__device__ float g_cX[DD];
__device__ float g_c[DD];
__device__ float g_cpart[32 * DD];

__device__ __nv_bfloat16 s_Xa[(size_t)NN * K3DD];
__device__ __nv_bfloat16 s_Wall[(size_t)NQK * K3DD];
__device__ __nv_bfloat16 s_Qa[(size_t)NN * K3HH];
__device__ __nv_bfloat16 s_Kb[(size_t)NN * K3HH];

// ---------------- mma.sync NT GEMM: 128x256 CTA, 64x64 warp, BK=64 ----------------
#define BM 128
#define BN 256
#define BK 64
#define STAGES 3
#define PAD 72
#define A_STAGE (BM * PAD * 2)
#define B_STAGE (BN * PAD * 2)
#define STAGE_BYTES (A_STAGE + B_STAGE)
#define GEMM_SMEM (STAGES * STAGE_BYTES)

__device__ __forceinline__ uint32_t smem_u32(const void* p) {
    uint32_t a;
    asm("{ .reg .u64 t; cvta.to.shared.u64 t, %1; cvt.u32.u64 %0, t; }" : "=r"(a) : "l"(p));
    return a;
}
#define CP_ASYNC16(sa, ga) \
    asm volatile("cp.async.cg.shared.global [%0], [%1], 16;" :: "r"(sa), "l"(ga))
#define CP_COMMIT() asm volatile("cp.async.commit_group;" ::: "memory")
#define CP_WAIT1()  asm volatile("cp.async.wait_group 1;" ::: "memory")
#define CP_WAIT0()  asm volatile("cp.async.wait_group 0;" ::: "memory")
#define LDSM_X4(r0, r1, r2, r3, a) \
    asm volatile("ldmatrix.sync.aligned.m8n8.x4.shared.b16 {%0,%1,%2,%3}, [%4];" \
        : "=r"(r0), "=r"(r1), "=r"(r2), "=r"(r3) : "r"(a))
#define MMA16816(c, a0, a1, a2, a3, b0, b1) \
    asm volatile("mma.sync.aligned.m16n8k16.row.col.f32.bf16.bf16.f32 " \
        "{%0,%1,%2,%3}, {%4,%5,%6,%7}, {%8,%9}, {%0,%1,%2,%3};" \
        : "+f"((c)[0]), "+f"((c)[1]), "+f"((c)[2]), "+f"((c)[3]) \
        : "r"(a0), "r"(a1), "r"(a2), "r"(a3), "r"(b0), "r"(b1))

__global__ __launch_bounds__(256) void mma_gemm_nt(
    const __nv_bfloat16* __restrict__ A, const __nv_bfloat16* __restrict__ B,
    float* __restrict__ C, int M, int N, int K, int ldc,
    const float* __restrict__ bias)
{
    extern __shared__ __align__(128) char smem[];
    const uint32_t sbase = smem_u32(smem);
    const int tid = threadIdx.x;
    const int wid = tid >> 5;
    const int lane = tid & 31;
    const int wm = (wid & 1) * 64;
    const int wn = (wid >> 1) * 64;

    const int nbx = gridDim.x;
    int id = blockIdx.y * nbx + blockIdx.x;
    int grp = id / (8 * nbx);
    int rem = id - grp * (8 * nbx);
    const int m0 = (grp * 8 + (rem & 7)) * BM;
    const int n0 = (rem >> 3) * BN;

    const __nv_bfloat16* gA = A + (size_t)m0 * K;
    const __nv_bfloat16* gB = B + (size_t)n0 * K;

    const int lrow = tid >> 3;
    const int lcol = (tid & 7) << 3;

    float acc[4][8][4];
    #pragma unroll
    for (int i = 0; i < 4; i++)
        #pragma unroll
        for (int j = 0; j < 8; j++)
            #pragma unroll
            for (int q = 0; q < 4; q++) acc[i][j][q] = 0.0f;

    const int KT = K / BK;

    #pragma unroll
    for (int s = 0; s < STAGES - 1; s++) {
        const int k0 = s * BK;
        uint32_t sa = sbase + s * STAGE_BYTES;
        uint32_t sb = sa + A_STAGE;
        #pragma unroll
        for (int h = 0; h < 4; h++) {
            int r = lrow + h * 32;
            CP_ASYNC16(sa + (uint32_t)(r * PAD + lcol) * 2, gA + (size_t)r * K + k0 + lcol);
        }
        #pragma unroll
        for (int h = 0; h < 8; h++) {
            int r = lrow + h * 32;
            CP_ASYNC16(sb + (uint32_t)(r * PAD + lcol) * 2, gB + (size_t)r * K + k0 + lcol);
        }
        CP_COMMIT();
    }

    const int a_row = wm + (lane & 15);
    const int a_half = (lane >> 4) << 3;
    const int b_row = wn + ((lane >> 4) << 3) + (lane & 7);
    const int b_half = ((lane >> 3) & 1) << 3;

    for (int kt = 0; kt < KT; kt++) {
        CP_WAIT1();
        __syncthreads();

        if (kt + STAGES - 1 < KT) {
            const int s = (kt + STAGES - 1) % STAGES;
            const int k0 = (kt + STAGES - 1) * BK;
            uint32_t sa = sbase + s * STAGE_BYTES;
            uint32_t sb = sa + A_STAGE;
            #pragma unroll
            for (int h = 0; h < 4; h++) {
                int r = lrow + h * 32;
                CP_ASYNC16(sa + (uint32_t)(r * PAD + lcol) * 2, gA + (size_t)r * K + k0 + lcol);
            }
            #pragma unroll
            for (int h = 0; h < 8; h++) {
                int r = lrow + h * 32;
                CP_ASYNC16(sb + (uint32_t)(r * PAD + lcol) * 2, gB + (size_t)r * K + k0 + lcol);
            }
        }
        CP_COMMIT();

        const int s = kt % STAGES;
        const uint32_t sa = sbase + s * STAGE_BYTES;
        const uint32_t sb = sa + A_STAGE;

        #pragma unroll
        for (int kk = 0; kk < 4; kk++) {
            uint32_t a0[4], a1[4], a2[4], a3[4];
            #pragma unroll
            for (int mt = 0; mt < 4; mt++) {
                uint32_t addr = sa + (uint32_t)((a_row + mt * 16) * PAD + kk * 16 + a_half) * 2;
                LDSM_X4(a0[mt], a1[mt], a2[mt], a3[mt], addr);
            }
            uint32_t b[8][2];
            #pragma unroll
            for (int g = 0; g < 4; g++) {
                uint32_t addr = sb + (uint32_t)((b_row + g * 16) * PAD + kk * 16 + b_half) * 2;
                uint32_t r0, r1, r2, r3;
                LDSM_X4(r0, r1, r2, r3, addr);
                b[g * 2 + 0][0] = r0; b[g * 2 + 0][1] = r1;
                b[g * 2 + 1][0] = r2; b[g * 2 + 1][1] = r3;
            }
            #pragma unroll
            for (int mt = 0; mt < 4; mt++)
                #pragma unroll
                for (int nt = 0; nt < 8; nt++)
                    MMA16816(acc[mt][nt], a0[mt], a1[mt], a2[mt], a3[mt],
                             b[nt][0], b[nt][1]);
        }
        __syncthreads();
    }
    CP_WAIT0();

    const int er = lane >> 2;
    const int ec = (lane & 3) << 1;
    #pragma unroll
    for (int mt = 0; mt < 4; mt++) {
        #pragma unroll
        for (int nt = 0; nt < 8; nt++) {
            int col = n0 + wn + nt * 8 + ec;
            float b0 = bias ? bias[col] : 0.0f;
            float b1 = bias ? bias[col + 1] : 0.0f;
            #pragma unroll
            for (int half = 0; half < 2; half++) {
                int row = m0 + wm + mt * 16 + er + half * 8;
                float* Cp = C + (size_t)row * ldc + col;
                *(float2*)Cp = make_float2(acc[mt][nt][half * 2 + 0] + b0,
                                           acc[mt][nt][half * 2 + 1] + b1);
            }
        }
    }
}

// ---------------- splits ----------------
__global__ void split_kernel(const float* __restrict__ src, __nv_bfloat16* __restrict__ dst,
                             int total, int logC, int lo_mid)
{
    int idx = blockIdx.x * blockDim.x + threadIdx.x;
    if (idx >= total) return;
    int C = 1 << logC;
    int r = idx >> logC;
    int c = idx & (C - 1);
    float x = src[idx];
    __nv_bfloat16 h = __float2bfloat16(x);
    __nv_bfloat16 l = __float2bfloat16(x - __bfloat162float(h));
    size_t base = (size_t)r * 3 * C + c;
    if (lo_mid) { dst[base] = h; dst[base + C] = l; dst[base + 2 * C] = h; }
    else        { dst[base] = h; dst[base + C] = h; dst[base + 2 * C] = l; }
}

__global__ void split_strided(const float* __restrict__ src, int srcld, int src_off,
                              __nv_bfloat16* __restrict__ dst, int rows, int lo_mid)
{
    int idx = blockIdx.x * blockDim.x + threadIdx.x;
    if (idx >= rows * HH) return;
    int r = idx >> 8;
    int c = idx & 255;
    float x = src[(size_t)r * srcld + src_off + c];
    __nv_bfloat16 h = __float2bfloat16(x);
    __nv_bfloat16 l = __float2bfloat16(x - __bfloat162float(h));
    size_t base = (size_t)r * 3 * HH + c;
    if (lo_mid) { dst[base] = h; dst[base + HH] = l; dst[base + 2 * HH] = h; }
    else        { dst[base] = h; dst[base + HH] = h; dst[base + 2 * HH] = l; }
}

__global__ void tofp16_kernel(const float* __restrict__ src, __half* __restrict__ dst, int n)
{
    int i = blockIdx.x * blockDim.x + threadIdx.x;
    if (i < n) dst[i] = __float2half(src[i]);
}

// ---------------- aux ----------------
__global__ void zero_kernel(float* out, int n) {
    int i = blockIdx.x * blockDim.x + threadIdx.x;
    if (i < n) out[i] = 0.0f;
}

__global__ void bias_build(const float* __restrict__ bq, const float* __restrict__ bk,
                           float* __restrict__ bias)
{
    int i = blockIdx.x * blockDim.x + threadIdx.x;
    if (i < 1024) bias[i] = bq[i];
    else if (i < 2048) bias[i] = bk[i - 1024];
}

__global__ void rownorm_kernel(const float* __restrict__ QK, int qoff, int koff,
                               float* __restrict__ qn, float* __restrict__ kn)
{
    int i = blockIdx.x;
    int tid = threadIdx.x;
    __shared__ float sq[256];
    __shared__ float sk[256];
    float q = QK[(size_t)i * NQK + qoff + tid];
    float k = QK[(size_t)i * NQK + koff + tid];
    sq[tid] = q * q;
    sk[tid] = k * k;
    __syncthreads();
    for (int s = 128; s > 0; s >>= 1) {
        if (tid < s) { sq[tid] += sq[tid + s]; sk[tid] += sk[tid + s]; }
        __syncthreads();
    }
    if (tid == 0) { qn[i] = sq[0]; kn[i] = sk[0]; }
}

__global__ void select_kernel(const float* __restrict__ G,
                              const float* __restrict__ qn, const float* __restrict__ kn,
                              float* __restrict__ md_out, float* __restrict__ kth_out)
{
    int i = blockIdx.x;
    int tid = threadIdx.x;
    __shared__ float sd[NN];
    __shared__ float rmin[256];
    __shared__ int ridx[256];
    __shared__ float sel[30];
    float qni = qn[i];
    const float* Gi = G + (size_t)i * NN;
    for (int j = tid; j < NN; j += 256) {
        float sq = qni + kn[j] - 2.0f * Gi[j];
        sd[j] = sqrtf(fmaxf(sq, 0.0f) + 1e-10f);
    }
    __syncthreads();
    for (int it = 0; it < 30; it++) {
        float mv = FLT_MAX;
        int mi = -1;
        for (int j = tid; j < NN; j += 256) {
            float v = sd[j];
            if (v < mv) { mv = v; mi = j; }
        }
        rmin[tid] = mv;
        ridx[tid] = mi;
        __syncthreads();
        for (int s = 128; s > 0; s >>= 1) {
            if (tid < s) {
                float v2 = rmin[tid + s];
                if (v2 < rmin[tid] || (v2 == rmin[tid] && ridx[tid + s] < ridx[tid])) {
                    rmin[tid] = v2;
                    ridx[tid] = ridx[tid + s];
                }
            }
            __syncthreads();
        }
        if (tid == 0) {
            sel[it] = rmin[0];
            sd[ridx[0]] = FLT_MAX;
        }
        __syncthreads();
    }
    if (tid == 0) {
        float mdp = sel[10] + 1e-10f;
        float t = sel[29] / mdp;
        md_out[i] = mdp;
        kth_out[i] = expf(-(t * t));
    }
}

// ---------------- fused aff + transpose-add: M = aff(G) + aff(G)^T ----------------
__global__ void afftrans_kernel(const float* __restrict__ G, float* __restrict__ M,
                                const float* __restrict__ qn, const float* __restrict__ kn,
                                const float* __restrict__ mdp, const float* __restrict__ kth)
{
    __shared__ float t[32][33];
    int x0 = blockIdx.x * 32;
    int y0 = blockIdx.y * 32;
    int tx = threadIdx.x;
    int ty = threadIdx.y;
    // load G[x-block rows][y-block cols]
    for (int r = ty; r < 32; r += 8)
        t[r][tx] = G[(size_t)(x0 + r) * NN + y0 + tx];
    __syncthreads();
    for (int r = ty; r < 32; r += 8) {
        int i = y0 + r;      // output row
        int j = x0 + tx;     // output col
        float gij = G[(size_t)i * NN + j];
        float sq1 = qn[i] + kn[j] - 2.0f * gij;
        float d1 = sqrtf(fmaxf(sq1, 0.0f) + 1e-10f) / mdp[i];
        float a1 = expf(-(d1 * d1));
        float r1 = (a1 >= kth[i]) ? a1 : 0.0f;
        float gji = t[tx][r]; // G[j][i]
        float sq2 = qn[j] + kn[i] - 2.0f * gji;
        float d2 = sqrtf(fmaxf(sq2, 0.0f) + 1e-10f) / mdp[j];
        float a2 = expf(-(d2 * d2));
        float r2 = (a2 >= kth[j]) ? a2 : 0.0f;
        if (i == j) { r1 = 1.0f; r2 = 1.0f; }
        M[(size_t)i * NN + j] = r1 + r2;
    }
}

// ---------------- sparse build (deterministic) ----------------
__global__ void build_sparse(const float* __restrict__ M, int* __restrict__ cols,
                             float* __restrict__ wv, int* __restrict__ cnt,
                             float* __restrict__ Z)
{
    int i = blockIdx.x;
    int t = threadIdx.x;
    __shared__ int sc[256];
    __shared__ float zr[256];
    const float* Mi = M + (size_t)i * NN;
    int c = 0;
    float zs = 0.0f;
    #pragma unroll
    for (int k = 0; k < 16; k++) {
        float v = Mi[t * 16 + k];
        if (v != 0.0f) { c++; zs += expf(v); }
    }
    sc[t] = c;
    zr[t] = zs;
    __syncthreads();
    for (int d = 1; d < 256; d <<= 1) {
        int x = (t >= d) ? sc[t - d] : 0;
        __syncthreads();
        sc[t] += x;
        __syncthreads();
    }
    int off = sc[t] - c;
    int total = sc[255];
    int p = 0;
    int* ci = cols + (size_t)i * SPW;
    float* wi = wv + (size_t)i * SPW;
    #pragma unroll
    for (int k = 0; k < 16; k++) {
        float v = Mi[t * 16 + k];
        if (v != 0.0f) {
            int o = off + p;
            if (o < SPW) { ci[o] = t * 16 + k; wi[o] = expf(v) - 1.0f; }
            p++;
        }
    }
    __syncthreads();
    for (int s = 128; s > 0; s >>= 1) {
        if (t < s) zr[t] += zr[t + s];
        __syncthreads();
    }
    if (t == 0) {
        int tt = total > SPW ? SPW : total;
        cnt[i] = tt;
        Z[i] = (float)(NN - total) + zr[0];
    }
}

// ---------------- colsums ----------------
__global__ void colsum_part_f(const float* __restrict__ Y, float* __restrict__ part)
{
    int col = blockIdx.x * 256 + threadIdx.x;
    int slab = blockIdx.y;
    float s = 0.0f;
    const float* p = Y + (size_t)slab * 128 * DD + col;
    #pragma unroll 4
    for (int r = 0; r < 128; r++) s += p[(size_t)r * DD];
    part[slab * DD + col] = s;
}
__global__ void colsum_part_h(const __half* __restrict__ Y, float* __restrict__ part)
{
    int col = blockIdx.x * 256 + threadIdx.x;
    int slab = blockIdx.y;
    float s = 0.0f;
    const __half* p = Y + (size_t)slab * 128 * DD + col;
    #pragma unroll 4
    for (int r = 0; r < 128; r++) s += __half2float(p[(size_t)r * DD]);
    part[slab * DD + col] = s;
}
__global__ void colsum_fin(const float* __restrict__ part, float* __restrict__ c)
{
    int col = blockIdx.x * 256 + threadIdx.x;
    float s = 0.0f;
    #pragma unroll
    for (int k = 0; k < 32; k++) s += part[k * DD + col];
    c[col] = s;
}

// ---------------- fp16 sparse applies ----------------
__global__ __launch_bounds__(256) void spmm_h(
    const int* __restrict__ cols, const float* __restrict__ wv,
    const int* __restrict__ cnt, const float* __restrict__ Z,
    const float* __restrict__ c, const __half* __restrict__ Yin,
    __half* __restrict__ Yout)
{
    const int i = blockIdx.y;
    const int d = blockIdx.x * 512 + threadIdx.x * 2;
    float a0 = c[d];
    float a1 = c[d + 1];
    const int n = cnt[i];
    const int* ci = cols + (size_t)i * SPW;
    const float* wi = wv + (size_t)i * SPW;
    #pragma unroll 4
    for (int k = 0; k < n; k++) {
        int j = ci[k];
        float w = wi[k];
        __half2 y = *(const __half2*)(Yin + (size_t)j * DD + d);
        float2 f = __half22float2(y);
        a0 = fmaf(w, f.x, a0);
        a1 = fmaf(w, f.y, a1);
    }
    float s = 1.0f / Z[i];
    *(__half2*)(Yout + (size_t)i * DD + d) = __floats2half2_rn(a0 * s, a1 * s);
}

__global__ __launch_bounds__(256) void spmm_h_out(
    const int* __restrict__ cols, const float* __restrict__ wv,
    const int* __restrict__ cnt, const float* __restrict__ Z,
    const float* __restrict__ c, const __half* __restrict__ Yin,
    float* __restrict__ out)
{
    const int i = blockIdx.y;
    const int d = blockIdx.x * 512 + threadIdx.x * 2;
    float a0 = c[d];
    float a1 = c[d + 1];
    const int n = cnt[i];
    const int* ci = cols + (size_t)i * SPW;
    const float* wi = wv + (size_t)i * SPW;
    #pragma unroll 4
    for (int k = 0; k < n; k++) {
        int j = ci[k];
        float w = wi[k];
        __half2 y = *(const __half2*)(Yin + (size_t)j * DD + d);
        float2 f = __half22float2(y);
        a0 = fmaf(w, f.x, a0);
        a1 = fmaf(w, f.y, a1);
    }
    float s = 0.25f / Z[i];
    float* o = out + (size_t)i * DD + d;
    o[0] += s * a0;
    o[1] += s * a1;
}

// ---------------- launch ----------------
static void run_gemm(const __nv_bfloat16* A, const __nv_bfloat16* B, float* C,
                     int M, int N, int K, int ldc, const float* bias)
{
    dim3 grid(N / BN, M / BM);
    mma_gemm_nt<<<grid, 256, GEMM_SMEM>>>(A, B, C, M, N, K, ldc, bias);
}

extern "C" void kernel_launch(void* const* d_in, const int* in_sizes, int n_in,
                              void* d_out, int out_size)
{
    const float* X  = (const float*)d_in[0];
    const float* Wq = (const float*)d_in[1];
    const float* bq = (const float*)d_in[2];
    const float* Wk = (const float*)d_in[3];
    const float* bk = (const float*)d_in[4];
    float* out = (float*)d_out;

    static int smem_set = 0;
    if (!smem_set) {
        cudaFuncSetAttribute(mma_gemm_nt, cudaFuncAttributeMaxDynamicSharedMemorySize,
                             GEMM_SMEM);
        smem_set = 1;
    }

    float *QK, *bias, *qn, *kn, *md, *kth, *A, *M;
    float *wv, *Z, *cX, *c, *cpart;
    int *cols, *cnt;
    __half *Xh, *Yh, *Y2h;
    __nv_bfloat16 *Xa, *Wall, *Qa, *Kb;
    cudaGetSymbolAddress((void**)&QK,   g_QK);
    cudaGetSymbolAddress((void**)&bias, g_bias);
    cudaGetSymbolAddress((void**)&qn,  g_qn);
    cudaGetSymbolAddress((void**)&kn,  g_kn);
    cudaGetSymbolAddress((void**)&md,  g_md);
    cudaGetSymbolAddress((void**)&kth, g_kth);
    cudaGetSymbolAddress((void**)&A,   g_A);
    cudaGetSymbolAddress((void**)&M,   g_M);
    cudaGetSymbolAddress((void**)&Xh,  h_X);
    cudaGetSymbolAddress((void**)&Yh,  h_Y);
    cudaGetSymbolAddress((void**)&Y2h, h_Y2);
    cudaGetSymbolAddress((void**)&cols, g_cols);
    cudaGetSymbolAddress((void**)&wv,   g_wv);
    cudaGetSymbolAddress((void**)&cnt,  g_cnt);
    cudaGetSymbolAddress((void**)&Z,    g_Z);
    cudaGetSymbolAddress((void**)&cX,   g_cX);
    cudaGetSymbolAddress((void**)&c,    g_c);
    cudaGetSymbolAddress((void**)&cpart, g_cpart);
    cudaGetSymbolAddress((void**)&Xa,   s_Xa);
    cudaGetSymbolAddress((void**)&Wall, s_Wall);
    cudaGetSymbolAddress((void**)&Qa,   s_Qa);
    cudaGetSymbolAddress((void**)&Kb,   s_Kb);

    // ---- setup ----
    split_kernel<<<(NN * DD + 255) / 256, 256>>>(X, Xa, NN * DD, 11, 1);
    split_kernel<<<(1024 * DD + 255) / 256, 256>>>(Wq, Wall, 1024 * DD, 11, 0);
    split_kernel<<<(1024 * DD + 255) / 256, 256>>>(Wk, Wall + (size_t)1024 * K3DD, 1024 * DD, 11, 0);
    bias_build<<<(NQK + 255) / 256, 256>>>(bq, bk, bias);
    tofp16_kernel<<<(NN * DD + 255) / 256, 256>>>(X, Xh, NN * DD);
    colsum_part_f<<<dim3(8, 32), 256>>>(X, cpart);
    colsum_fin<<<8, 256>>>(cpart, cX);
    zero_kernel<<<(NN * DD + 255) / 256, 256>>>(out, NN * DD);

    // combined projections
    run_gemm(Xa, Wall, QK, NN, NQK, K3DD, NQK, bias);

    for (int h = 0; h < HEADS; h++) {
        const int qoff = h * HH;
        const int koff = 1024 + h * HH;

        rownorm_kernel<<<NN, 256>>>(QK, qoff, koff, qn, kn);
        split_strided<<<(NN * HH + 255) / 256, 256>>>(QK, NQK, qoff, Qa, NN, 1);
        split_strided<<<(NN * HH + 255) / 256, 256>>>(QK, NQK, koff, Kb, NN, 0);
        run_gemm(Qa, Kb, A, NN, NN, K3HH, NN, nullptr);

        select_kernel<<<NN, 256>>>(A, qn, kn, md, kth);
        afftrans_kernel<<<dim3(NN / 32, NN / 32), dim3(32, 8)>>>(A, M, qn, kn, md, kth);
        build_sparse<<<NN, 256>>>(M, cols, wv, cnt, Z);

        dim3 sg(4, NN);
        // a1: Y = P X   (gather fp16 X, exact fp32 colsum of X)
        spmm_h<<<sg, 256>>>(cols, wv, cnt, Z, cX, Xh, Yh);
        colsum_part_h<<<dim3(8, 32), 256>>>(Yh, cpart);
        colsum_fin<<<8, 256>>>(cpart, c);
        // a2
        spmm_h<<<sg, 256>>>(cols, wv, cnt, Z, c, Yh, Y2h);
        colsum_part_h<<<dim3(8, 32), 256>>>(Y2h, cpart);
        colsum_fin<<<8, 256>>>(cpart, c);
        // a3
        spmm_h<<<sg, 256>>>(cols, wv, cnt, Z, c, Y2h, Yh);
        colsum_part_h<<<dim3(8, 32), 256>>>(Yh, cpart);
        colsum_fin<<<8, 256>>>(cpart, c);
        // a4
        spmm_h<<<sg, 256>>>(cols, wv, cnt, Z, c, Yh, Y2h);
        colsum_part_h<<<dim3(8, 32), 256>>>(Y2h, cpart);
        colsum_fin<<<8, 256>>>(cpart, c);
        // a5
        spmm_h<<<sg, 256>>>(cols, wv, cnt, Z, c, Y2h, Yh);
        colsum_part_h<<<dim3(8, 32), 256>>>(Yh, cpart);
        colsum_fin<<<8, 256>>>(cpart, c);
        // a6: out += 0.25 * P Y
        spmm_h_out<<<sg, 256>>>(cols, wv, cnt, Z, c, Yh, out);
    }
}

// round 9
// speedup vs baseline: 9.9625x; 1.4814x over previous
#include <cuda_runtime.h>
#include <cuda_bf16.h>
#include <cuda_fp16.h>
#include <math.h>
#include <float.h>
#include <stdint.h>

#define NN 4096
#define DD 2048
#define HH 256
#define HEADS 4
#define K3DD (3*2048)
#define K3HH (3*256)
#define NQK 2048
#define SPW 2048

// ---------------- static device scratch (per-head slices) ----------------
__device__ float g_QK[(size_t)NN * NQK];
__device__ float g_bias[NQK];
__device__ float g_qn[HEADS * NN];
__device__ float g_kn[HEADS * NN];
__device__ float g_md[HEADS * NN];
__device__ float g_kth[HEADS * NN];
__device__ float g_A[(size_t)HEADS * NN * NN];
__device__ float g_M[(size_t)HEADS * NN * NN];
__device__ __half h_X[(size_t)NN * DD];
__device__ __half h_Y[(size_t)HEADS * NN * DD];
__device__ __half h_Y2[(size_t)HEADS * NN * DD];
__device__ float g_ctx[(size_t)HEADS * NN * DD];

__device__ int   g_cols[(size_t)HEADS * NN * SPW];
__device__ float g_wv[(size_t)HEADS * NN * SPW];
__device__ int   g_cnt[HEADS * NN];
__device__ float g_Z[HEADS * NN];
__device__ float g_cX[DD];
__device__ float g_c[HEADS * DD];
__device__ float g_cpart[HEADS * 32 * DD];

__device__ __nv_bfloat16 s_Xa[(size_t)NN * K3DD];
__device__ __nv_bfloat16 s_Wall[(size_t)NQK * K3DD];
__device__ __nv_bfloat16 s_Qa[(size_t)HEADS * NN * K3HH];
__device__ __nv_bfloat16 s_Kb[(size_t)HEADS * NN * K3HH];

// ---------------- batched mma.sync NT GEMM: 128x256 CTA, 64x64 warp, BK=64 ----------------
#define BM 128
#define BN 256
#define BK 64
#define STAGES 3
#define PAD 72
#define A_STAGE (BM * PAD * 2)
#define B_STAGE (BN * PAD * 2)
#define STAGE_BYTES (A_STAGE + B_STAGE)
#define GEMM_SMEM (STAGES * STAGE_BYTES)

__device__ __forceinline__ uint32_t smem_u32(const void* p) {
    uint32_t a;
    asm("{ .reg .u64 t; cvta.to.shared.u64 t, %1; cvt.u32.u64 %0, t; }" : "=r"(a) : "l"(p));
    return a;
}
#define CP_ASYNC16(sa, ga) \
    asm volatile("cp.async.cg.shared.global [%0], [%1], 16;" :: "r"(sa), "l"(ga))
#define CP_COMMIT() asm volatile("cp.async.commit_group;" ::: "memory")
#define CP_WAIT1()  asm volatile("cp.async.wait_group 1;" ::: "memory")
#define CP_WAIT0()  asm volatile("cp.async.wait_group 0;" ::: "memory")
#define LDSM_X4(r0, r1, r2, r3, a) \
    asm volatile("ldmatrix.sync.aligned.m8n8.x4.shared.b16 {%0,%1,%2,%3}, [%4];" \
        : "=r"(r0), "=r"(r1), "=r"(r2), "=r"(r3) : "r"(a))
#define MMA16816(c, a0, a1, a2, a3, b0, b1) \
    asm volatile("mma.sync.aligned.m16n8k16.row.col.f32.bf16.bf16.f32 " \
        "{%0,%1,%2,%3}, {%4,%5,%6,%7}, {%8,%9}, {%0,%1,%2,%3};" \
        : "+f"((c)[0]), "+f"((c)[1]), "+f"((c)[2]), "+f"((c)[3]) \
        : "r"(a0), "r"(a1), "r"(a2), "r"(a3), "r"(b0), "r"(b1))

__global__ __launch_bounds__(256) void mma_gemm_nt(
    const __nv_bfloat16* __restrict__ Ab, const __nv_bfloat16* __restrict__ Bb,
    float* __restrict__ Cb, int M, int N, int K, int ldc,
    size_t strideA, size_t strideB, size_t strideC,
    const float* __restrict__ bias)
{
    extern __shared__ __align__(128) char smem[];
    const uint32_t sbase = smem_u32(smem);
    const int tid = threadIdx.x;
    const int wid = tid >> 5;
    const int lane = tid & 31;
    const int wm = (wid & 1) * 64;
    const int wn = (wid >> 1) * 64;

    const __nv_bfloat16* A = Ab + blockIdx.z * strideA;
    const __nv_bfloat16* B = Bb + blockIdx.z * strideB;
    float* C = Cb + blockIdx.z * strideC;

    const int nbx = gridDim.x;
    int id = blockIdx.y * nbx + blockIdx.x;
    int grp = id / (8 * nbx);
    int rem = id - grp * (8 * nbx);
    const int m0 = (grp * 8 + (rem & 7)) * BM;
    const int n0 = (rem >> 3) * BN;

    const __nv_bfloat16* gA = A + (size_t)m0 * K;
    const __nv_bfloat16* gB = B + (size_t)n0 * K;

    const int lrow = tid >> 3;
    const int lcol = (tid & 7) << 3;

    float acc[4][8][4];
    #pragma unroll
    for (int i = 0; i < 4; i++)
        #pragma unroll
        for (int j = 0; j < 8; j++)
            #pragma unroll
            for (int q = 0; q < 4; q++) acc[i][j][q] = 0.0f;

    const int KT = K / BK;

    #pragma unroll
    for (int s = 0; s < STAGES - 1; s++) {
        const int k0 = s * BK;
        uint32_t sa = sbase + s * STAGE_BYTES;
        uint32_t sb = sa + A_STAGE;
        #pragma unroll
        for (int h = 0; h < 4; h++) {
            int r = lrow + h * 32;
            CP_ASYNC16(sa + (uint32_t)(r * PAD + lcol) * 2, gA + (size_t)r * K + k0 + lcol);
        }
        #pragma unroll
        for (int h = 0; h < 8; h++) {
            int r = lrow + h * 32;
            CP_ASYNC16(sb + (uint32_t)(r * PAD + lcol) * 2, gB + (size_t)r * K + k0 + lcol);
        }
        CP_COMMIT();
    }

    const int a_row = wm + (lane & 15);
    const int a_half = (lane >> 4) << 3;
    const int b_row = wn + ((lane >> 4) << 3) + (lane & 7);
    const int b_half = ((lane >> 3) & 1) << 3;

    for (int kt = 0; kt < KT; kt++) {
        CP_WAIT1();
        __syncthreads();

        if (kt + STAGES - 1 < KT) {
            const int s = (kt + STAGES - 1) % STAGES;
            const int k0 = (kt + STAGES - 1) * BK;
            uint32_t sa = sbase + s * STAGE_BYTES;
            uint32_t sb = sa + A_STAGE;
            #pragma unroll
            for (int h = 0; h < 4; h++) {
                int r = lrow + h * 32;
                CP_ASYNC16(sa + (uint32_t)(r * PAD + lcol) * 2, gA + (size_t)r * K + k0 + lcol);
            }
            #pragma unroll
            for (int h = 0; h < 8; h++) {
                int r = lrow + h * 32;
                CP_ASYNC16(sb + (uint32_t)(r * PAD + lcol) * 2, gB + (size_t)r * K + k0 + lcol);
            }
        }
        CP_COMMIT();

        const int s = kt % STAGES;
        const uint32_t sa = sbase + s * STAGE_BYTES;
        const uint32_t sb = sa + A_STAGE;

        #pragma unroll
        for (int kk = 0; kk < 4; kk++) {
            uint32_t a0[4], a1[4], a2[4], a3[4];
            #pragma unroll
            for (int mt = 0; mt < 4; mt++) {
                uint32_t addr = sa + (uint32_t)((a_row + mt * 16) * PAD + kk * 16 + a_half) * 2;
                LDSM_X4(a0[mt], a1[mt], a2[mt], a3[mt], addr);
            }
            uint32_t b[8][2];
            #pragma unroll
            for (int g = 0; g < 4; g++) {
                uint32_t addr = sb + (uint32_t)((b_row + g * 16) * PAD + kk * 16 + b_half) * 2;
                uint32_t r0, r1, r2, r3;
                LDSM_X4(r0, r1, r2, r3, addr);
                b[g * 2 + 0][0] = r0; b[g * 2 + 0][1] = r1;
                b[g * 2 + 1][0] = r2; b[g * 2 + 1][1] = r3;
            }
            #pragma unroll
            for (int mt = 0; mt < 4; mt++)
                #pragma unroll
                for (int nt = 0; nt < 8; nt++)
                    MMA16816(acc[mt][nt], a0[mt], a1[mt], a2[mt], a3[mt],
                             b[nt][0], b[nt][1]);
        }
        __syncthreads();
    }
    CP_WAIT0();

    const int er = lane >> 2;
    const int ec = (lane & 3) << 1;
    #pragma unroll
    for (int mt = 0; mt < 4; mt++) {
        #pragma unroll
        for (int nt = 0; nt < 8; nt++) {
            int col = n0 + wn + nt * 8 + ec;
            float b0 = bias ? bias[col] : 0.0f;
            float b1 = bias ? bias[col + 1] : 0.0f;
            #pragma unroll
            for (int half = 0; half < 2; half++) {
                int row = m0 + wm + mt * 16 + er + half * 8;
                float* Cp = C + (size_t)row * ldc + col;
                *(float2*)Cp = make_float2(acc[mt][nt][half * 2 + 0] + b0,
                                           acc[mt][nt][half * 2 + 1] + b1);
            }
        }
    }
}

// ---------------- splits ----------------
__global__ void split_kernel(const float* __restrict__ src, __nv_bfloat16* __restrict__ dst,
                             int total, int logC, int lo_mid)
{
    int idx = blockIdx.x * blockDim.x + threadIdx.x;
    if (idx >= total) return;
    int C = 1 << logC;
    int r = idx >> logC;
    int c = idx & (C - 1);
    float x = src[idx];
    __nv_bfloat16 h = __float2bfloat16(x);
    __nv_bfloat16 l = __float2bfloat16(x - __bfloat162float(h));
    size_t base = (size_t)r * 3 * C + c;
    if (lo_mid) { dst[base] = h; dst[base + C] = l; dst[base + 2 * C] = h; }
    else        { dst[base] = h; dst[base + C] = h; dst[base + 2 * C] = l; }
}

// batched over heads: blockIdx.y = head
__global__ void split_strided_b(const float* __restrict__ QK, int base_off,
                                __nv_bfloat16* __restrict__ dst, int lo_mid)
{
    int idx = blockIdx.x * blockDim.x + threadIdx.x;
    if (idx >= NN * HH) return;
    int h = blockIdx.y;
    int r = idx >> 8;
    int c = idx & 255;
    float x = QK[(size_t)r * NQK + base_off + h * HH + c];
    __nv_bfloat16 hi = __float2bfloat16(x);
    __nv_bfloat16 lo = __float2bfloat16(x - __bfloat162float(hi));
    size_t base = (size_t)h * NN * K3HH + (size_t)r * 3 * HH + c;
    if (lo_mid) { dst[base] = hi; dst[base + HH] = lo; dst[base + 2 * HH] = hi; }
    else        { dst[base] = hi; dst[base + HH] = hi; dst[base + 2 * HH] = lo; }
}

__global__ void tofp16_kernel(const float* __restrict__ src, __half* __restrict__ dst, int n)
{
    int i = blockIdx.x * blockDim.x + threadIdx.x;
    if (i < n) dst[i] = __float2half(src[i]);
}

// ---------------- aux ----------------
__global__ void bias_build(const float* __restrict__ bq, const float* __restrict__ bk,
                           float* __restrict__ bias)
{
    int i = blockIdx.x * blockDim.x + threadIdx.x;
    if (i < 1024) bias[i] = bq[i];
    else if (i < 2048) bias[i] = bk[i - 1024];
}

// batched: blockIdx.y = head
__global__ void rownorm_b(const float* __restrict__ QK,
                          float* __restrict__ qn, float* __restrict__ kn)
{
    int i = blockIdx.x;
    int h = blockIdx.y;
    int tid = threadIdx.x;
    __shared__ float sq[256];
    __shared__ float sk[256];
    float q = QK[(size_t)i * NQK + h * HH + tid];
    float k = QK[(size_t)i * NQK + 1024 + h * HH + tid];
    sq[tid] = q * q;
    sk[tid] = k * k;
    __syncthreads();
    for (int s = 128; s > 0; s >>= 1) {
        if (tid < s) { sq[tid] += sq[tid + s]; sk[tid] += sk[tid + s]; }
        __syncthreads();
    }
    if (tid == 0) { qn[h * NN + i] = sq[0]; kn[h * NN + i] = sk[0]; }
}

// batched: blockIdx.y = head
__global__ void select_b(const float* __restrict__ Ab,
                         const float* __restrict__ qn, const float* __restrict__ kn,
                         float* __restrict__ md_out, float* __restrict__ kth_out)
{
    int i = blockIdx.x;
    int h = blockIdx.y;
    int tid = threadIdx.x;
    __shared__ float sd[NN];
    __shared__ float rmin[256];
    __shared__ int ridx[256];
    __shared__ float sel[30];
    const float* G = Ab + (size_t)h * NN * NN;
    const float* qnh = qn + h * NN;
    const float* knh = kn + h * NN;
    float qni = qnh[i];
    const float* Gi = G + (size_t)i * NN;
    for (int j = tid; j < NN; j += 256) {
        float sq = qni + knh[j] - 2.0f * Gi[j];
        sd[j] = sqrtf(fmaxf(sq, 0.0f) + 1e-10f);
    }
    __syncthreads();
    for (int it = 0; it < 30; it++) {
        float mv = FLT_MAX;
        int mi = -1;
        for (int j = tid; j < NN; j += 256) {
            float v = sd[j];
            if (v < mv) { mv = v; mi = j; }
        }
        rmin[tid] = mv;
        ridx[tid] = mi;
        __syncthreads();
        for (int s = 128; s > 0; s >>= 1) {
            if (tid < s) {
                float v2 = rmin[tid + s];
                if (v2 < rmin[tid] || (v2 == rmin[tid] && ridx[tid + s] < ridx[tid])) {
                    rmin[tid] = v2;
                    ridx[tid] = ridx[tid + s];
                }
            }
            __syncthreads();
        }
        if (tid == 0) {
            sel[it] = rmin[0];
            sd[ridx[0]] = FLT_MAX;
        }
        __syncthreads();
    }
    if (tid == 0) {
        float mdp = sel[10] + 1e-10f;
        float t = sel[29] / mdp;
        md_out[h * NN + i] = mdp;
        kth_out[h * NN + i] = expf(-(t * t));
    }
}

// batched fused aff + transpose-add: blockIdx.z = head
__global__ void afftrans_b(const float* __restrict__ Ab, float* __restrict__ Mb,
                           const float* __restrict__ qn, const float* __restrict__ kn,
                           const float* __restrict__ mdp, const float* __restrict__ kth)
{
    __shared__ float t[32][33];
    int hh = blockIdx.z;
    const float* G = Ab + (size_t)hh * NN * NN;
    float* M = Mb + (size_t)hh * NN * NN;
    const float* qnh = qn + hh * NN;
    const float* knh = kn + hh * NN;
    const float* mdh = mdp + hh * NN;
    const float* kthh = kth + hh * NN;
    int x0 = blockIdx.x * 32;
    int y0 = blockIdx.y * 32;
    int tx = threadIdx.x;
    int ty = threadIdx.y;
    for (int r = ty; r < 32; r += 8)
        t[r][tx] = G[(size_t)(x0 + r) * NN + y0 + tx];
    __syncthreads();
    for (int r = ty; r < 32; r += 8) {
        int i = y0 + r;
        int j = x0 + tx;
        float gij = G[(size_t)i * NN + j];
        float sq1 = qnh[i] + knh[j] - 2.0f * gij;
        float d1 = sqrtf(fmaxf(sq1, 0.0f) + 1e-10f) / mdh[i];
        float a1 = expf(-(d1 * d1));
        float r1 = (a1 >= kthh[i]) ? a1 : 0.0f;
        float gji = t[tx][r];
        float sq2 = qnh[j] + knh[i] - 2.0f * gji;
        float d2 = sqrtf(fmaxf(sq2, 0.0f) + 1e-10f) / mdh[j];
        float a2 = expf(-(d2 * d2));
        float r2 = (a2 >= kthh[j]) ? a2 : 0.0f;
        if (i == j) { r1 = 1.0f; r2 = 1.0f; }
        M[(size_t)i * NN + j] = r1 + r2;
    }
}

// batched sparse build: blockIdx.y = head
__global__ void build_sparse_b(const float* __restrict__ Mb, int* __restrict__ cols,
                               float* __restrict__ wv, int* __restrict__ cnt,
                               float* __restrict__ Z)
{
    int i = blockIdx.x;
    int h = blockIdx.y;
    int t = threadIdx.x;
    __shared__ int sc[256];
    __shared__ float zr[256];
    const float* Mi = Mb + (size_t)h * NN * NN + (size_t)i * NN;
    int c = 0;
    float zs = 0.0f;
    #pragma unroll
    for (int k = 0; k < 16; k++) {
        float v = Mi[t * 16 + k];
        if (v != 0.0f) { c++; zs += expf(v); }
    }
    sc[t] = c;
    zr[t] = zs;
    __syncthreads();
    for (int d = 1; d < 256; d <<= 1) {
        int x = (t >= d) ? sc[t - d] : 0;
        __syncthreads();
        sc[t] += x;
        __syncthreads();
    }
    int off = sc[t] - c;
    int total = sc[255];
    int p = 0;
    int* ci = cols + ((size_t)h * NN + i) * SPW;
    float* wi = wv + ((size_t)h * NN + i) * SPW;
    #pragma unroll
    for (int k = 0; k < 16; k++) {
        float v = Mi[t * 16 + k];
        if (v != 0.0f) {
            int o = off + p;
            if (o < SPW) { ci[o] = t * 16 + k; wi[o] = expf(v) - 1.0f; }
            p++;
        }
    }
    __syncthreads();
    for (int s = 128; s > 0; s >>= 1) {
        if (t < s) zr[t] += zr[t + s];
        __syncthreads();
    }
    if (t == 0) {
        int tt = total > SPW ? SPW : total;
        cnt[h * NN + i] = tt;
        Z[h * NN + i] = (float)(NN - total) + zr[0];
    }
}

// ---------------- colsums ----------------
__global__ void colsum_part_f(const float* __restrict__ Y, float* __restrict__ part)
{
    int col = blockIdx.x * 256 + threadIdx.x;
    int slab = blockIdx.y;
    float s = 0.0f;
    const float* p = Y + (size_t)slab * 128 * DD + col;
    #pragma unroll 4
    for (int r = 0; r < 128; r++) s += p[(size_t)r * DD];
    part[slab * DD + col] = s;
}
// batched: blockIdx.z = head
__global__ void colsum_part_hb(const __half* __restrict__ Yb, float* __restrict__ part)
{
    int col = blockIdx.x * 256 + threadIdx.x;
    int slab = blockIdx.y;
    int h = blockIdx.z;
    float s = 0.0f;
    const __half* p = Yb + (size_t)h * NN * DD + (size_t)slab * 128 * DD + col;
    #pragma unroll 4
    for (int r = 0; r < 128; r++) s += __half2float(p[(size_t)r * DD]);
    part[(size_t)h * 32 * DD + slab * DD + col] = s;
}
// batched: blockIdx.y = head
__global__ void colsum_fin_b(const float* __restrict__ part, float* __restrict__ c)
{
    int col = blockIdx.x * 256 + threadIdx.x;
    int h = blockIdx.y;
    const float* ph = part + (size_t)h * 32 * DD;
    float s = 0.0f;
    #pragma unroll
    for (int k = 0; k < 32; k++) s += ph[k * DD + col];
    c[h * DD + col] = s;
}

// ---------------- batched spmm: grid (NN, HEADS) ----------------
// c stride selectable (0 = shared cX), Yin stride selectable (0 = shared Xh)
__global__ __launch_bounds__(256) void spmm_b(
    const int* __restrict__ cols, const float* __restrict__ wv,
    const int* __restrict__ cnt, const float* __restrict__ Z,
    const float* __restrict__ c, int cstride,
    const __half* __restrict__ Yin, int yin_per_head,
    __half* __restrict__ Yout)
{
    const int i = blockIdx.x;
    const int h = blockIdx.y;
    const int d = threadIdx.x * 8;
    __shared__ int sj[SPW];
    __shared__ float sw[SPW];
    const int n = cnt[h * NN + i];
    const int* ci = cols + ((size_t)h * NN + i) * SPW;
    const float* wi = wv + ((size_t)h * NN + i) * SPW;
    for (int k = threadIdx.x; k < n; k += 256) { sj[k] = ci[k]; sw[k] = wi[k]; }
    __syncthreads();
    const float* ch = c + (size_t)h * cstride;
    const __half* Yh = Yin + (yin_per_head ? (size_t)h * NN * DD : 0);
    float a[8];
    #pragma unroll
    for (int q = 0; q < 8; q++) a[q] = ch[d + q];
    #pragma unroll 4
    for (int k = 0; k < n; k++) {
        int j = sj[k];
        float w = sw[k];
        uint4 v = *(const uint4*)(Yh + (size_t)j * DD + d);
        const __half2* hv = (const __half2*)&v;
        #pragma unroll
        for (int q = 0; q < 4; q++) {
            float2 f = __half22float2(hv[q]);
            a[2 * q + 0] = fmaf(w, f.x, a[2 * q + 0]);
            a[2 * q + 1] = fmaf(w, f.y, a[2 * q + 1]);
        }
    }
    float s = 1.0f / Z[h * NN + i];
    uint4 o;
    __half2* ho = (__half2*)&o;
    #pragma unroll
    for (int q = 0; q < 4; q++)
        ho[q] = __floats2half2_rn(a[2 * q] * s, a[2 * q + 1] * s);
    *(uint4*)(Yout + (size_t)h * NN * DD + (size_t)i * DD + d) = o;
}

__global__ __launch_bounds__(256) void spmm_ctx_b(
    const int* __restrict__ cols, const float* __restrict__ wv,
    const int* __restrict__ cnt, const float* __restrict__ Z,
    const float* __restrict__ c, const __half* __restrict__ Yin,
    float* __restrict__ ctx)
{
    const int i = blockIdx.x;
    const int h = blockIdx.y;
    const int d = threadIdx.x * 8;
    __shared__ int sj[SPW];
    __shared__ float sw[SPW];
    const int n = cnt[h * NN + i];
    const int* ci = cols + ((size_t)h * NN + i) * SPW;
    const float* wi = wv + ((size_t)h * NN + i) * SPW;
    for (int k = threadIdx.x; k < n; k += 256) { sj[k] = ci[k]; sw[k] = wi[k]; }
    __syncthreads();
    const float* ch = c + (size_t)h * DD;
    const __half* Yh = Yin + (size_t)h * NN * DD;
    float a[8];
    #pragma unroll
    for (int q = 0; q < 8; q++) a[q] = ch[d + q];
    #pragma unroll 4
    for (int k = 0; k < n; k++) {
        int j = sj[k];
        float w = sw[k];
        uint4 v = *(const uint4*)(Yh + (size_t)j * DD + d);
        const __half2* hv = (const __half2*)&v;
        #pragma unroll
        for (int q = 0; q < 4; q++) {
            float2 f = __half22float2(hv[q]);
            a[2 * q + 0] = fmaf(w, f.x, a[2 * q + 0]);
            a[2 * q + 1] = fmaf(w, f.y, a[2 * q + 1]);
        }
    }
    float s = 1.0f / Z[h * NN + i];
    float* o = ctx + (size_t)h * NN * DD + (size_t)i * DD + d;
    #pragma unroll
    for (int q = 0; q < 8; q++) o[q] = a[q] * s;
}

// ---------------- final join ----------------
__global__ void join_kernel(const float* __restrict__ ctx, float* __restrict__ out)
{
    size_t idx = (size_t)blockIdx.x * 256 + threadIdx.x;
    float s = ctx[idx]
            + ctx[idx + (size_t)NN * DD]
            + ctx[idx + 2 * (size_t)NN * DD]
            + ctx[idx + 3 * (size_t)NN * DD];
    out[idx] = 0.25f * s;
}

// ---------------- launch ----------------
extern "C" void kernel_launch(void* const* d_in, const int* in_sizes, int n_in,
                              void* d_out, int out_size)
{
    const float* X  = (const float*)d_in[0];
    const float* Wq = (const float*)d_in[1];
    const float* bq = (const float*)d_in[2];
    const float* Wk = (const float*)d_in[3];
    const float* bk = (const float*)d_in[4];
    float* out = (float*)d_out;

    static int smem_set = 0;
    if (!smem_set) {
        cudaFuncSetAttribute(mma_gemm_nt, cudaFuncAttributeMaxDynamicSharedMemorySize,
                             GEMM_SMEM);
        smem_set = 1;
    }

    float *QK, *bias, *qn, *kn, *md, *kth, *A, *M, *ctx;
    float *wv, *Z, *cX, *c, *cpart;
    int *cols, *cnt;
    __half *Xh, *Yh, *Y2h;
    __nv_bfloat16 *Xa, *Wall, *Qa, *Kb;
    cudaGetSymbolAddress((void**)&QK,   g_QK);
    cudaGetSymbolAddress((void**)&bias, g_bias);
    cudaGetSymbolAddress((void**)&qn,  g_qn);
    cudaGetSymbolAddress((void**)&kn,  g_kn);
    cudaGetSymbolAddress((void**)&md,  g_md);
    cudaGetSymbolAddress((void**)&kth, g_kth);
    cudaGetSymbolAddress((void**)&A,   g_A);
    cudaGetSymbolAddress((void**)&M,   g_M);
    cudaGetSymbolAddress((void**)&ctx, g_ctx);
    cudaGetSymbolAddress((void**)&Xh,  h_X);
    cudaGetSymbolAddress((void**)&Yh,  h_Y);
    cudaGetSymbolAddress((void**)&Y2h, h_Y2);
    cudaGetSymbolAddress((void**)&cols, g_cols);
    cudaGetSymbolAddress((void**)&wv,   g_wv);
    cudaGetSymbolAddress((void**)&cnt,  g_cnt);
    cudaGetSymbolAddress((void**)&Z,    g_Z);
    cudaGetSymbolAddress((void**)&cX,   g_cX);
    cudaGetSymbolAddress((void**)&c,    g_c);
    cudaGetSymbolAddress((void**)&cpart, g_cpart);
    cudaGetSymbolAddress((void**)&Xa,   s_Xa);
    cudaGetSymbolAddress((void**)&Wall, s_Wall);
    cudaGetSymbolAddress((void**)&Qa,   s_Qa);
    cudaGetSymbolAddress((void**)&Kb,   s_Kb);

    const size_t SA = (size_t)NN * K3HH;
    const size_t SC = (size_t)NN * NN;

    // ---- setup ----
    split_kernel<<<(NN * DD + 255) / 256, 256>>>(X, Xa, NN * DD, 11, 1);
    split_kernel<<<(1024 * DD + 255) / 256, 256>>>(Wq, Wall, 1024 * DD, 11, 0);
    split_kernel<<<(1024 * DD + 255) / 256, 256>>>(Wk, Wall + (size_t)1024 * K3DD, 1024 * DD, 11, 0);
    bias_build<<<(NQK + 255) / 256, 256>>>(bq, bk, bias);
    tofp16_kernel<<<(NN * DD + 255) / 256, 256>>>(X, Xh, NN * DD);
    colsum_part_f<<<dim3(8, 32), 256>>>(X, cpart);
    colsum_fin_b<<<dim3(8, 1), 256>>>(cpart, cX);

    // combined projections (batch=1)
    mma_gemm_nt<<<dim3(NQK / BN, NN / BM, 1), 256, GEMM_SMEM>>>(
        Xa, Wall, QK, NN, NQK, K3DD, NQK, 0, 0, 0, bias);

    // ---- per-head phases, all heads batched per launch ----
    rownorm_b<<<dim3(NN, HEADS), 256>>>(QK, qn, kn);
    split_strided_b<<<dim3((NN * HH + 255) / 256, HEADS), 256>>>(QK, 0, Qa, 1);
    split_strided_b<<<dim3((NN * HH + 255) / 256, HEADS), 256>>>(QK, 1024, Kb, 0);
    mma_gemm_nt<<<dim3(NN / BN, NN / BM, HEADS), 256, GEMM_SMEM>>>(
        Qa, Kb, A, NN, NN, K3HH, NN, SA, SA, SC, nullptr);

    select_b<<<dim3(NN, HEADS), 256>>>(A, qn, kn, md, kth);
    afftrans_b<<<dim3(NN / 32, NN / 32, HEADS), dim3(32, 8)>>>(A, M, qn, kn, md, kth);
    build_sparse_b<<<dim3(NN, HEADS), 256>>>(M, cols, wv, cnt, Z);

    dim3 sg(NN, HEADS);
    // a1: Y = P X (shared input, shared colsum)
    spmm_b<<<sg, 256>>>(cols, wv, cnt, Z, cX, 0, Xh, 0, Yh);
    colsum_part_hb<<<dim3(8, 32, HEADS), 256>>>(Yh, cpart);
    colsum_fin_b<<<dim3(8, HEADS), 256>>>(cpart, c);
    // a2
    spmm_b<<<sg, 256>>>(cols, wv, cnt, Z, c, DD, Yh, 1, Y2h);
    colsum_part_hb<<<dim3(8, 32, HEADS), 256>>>(Y2h, cpart);
    colsum_fin_b<<<dim3(8, HEADS), 256>>>(cpart, c);
    // a3
    spmm_b<<<sg, 256>>>(cols, wv, cnt, Z, c, DD, Y2h, 1, Yh);
    colsum_part_hb<<<dim3(8, 32, HEADS), 256>>>(Yh, cpart);
    colsum_fin_b<<<dim3(8, HEADS), 256>>>(cpart, c);
    // a4
    spmm_b<<<sg, 256>>>(cols, wv, cnt, Z, c, DD, Yh, 1, Y2h);
    colsum_part_hb<<<dim3(8, 32, HEADS), 256>>>(Y2h, cpart);
    colsum_fin_b<<<dim3(8, HEADS), 256>>>(cpart, c);
    // a5
    spmm_b<<<sg, 256>>>(cols, wv, cnt, Z, c, DD, Y2h, 1, Yh);
    colsum_part_hb<<<dim3(8, 32, HEADS), 256>>>(Yh, cpart);
    colsum_fin_b<<<dim3(8, HEADS), 256>>>(cpart, c);
    // a6: ctx = P Y
    spmm_ctx_b<<<sg, 256>>>(cols, wv, cnt, Z, c, Yh, ctx);

    join_kernel<<<(NN * DD) / 256, 256>>>(ctx, out);
}